// round 13
// baseline (speedup 1.0000x reference)
#include <cuda_runtime.h>
#include <cuda_fp16.h>
#include <cstdint>
#include <math.h>

#define H       256
#define FH      1024
#define NNODE   20000
#define NEDGE   160000
#define NLG     640000

// ---------------- scratch (static device memory; no allocations) ----------------
__device__ __half h_x[2][(size_t)NNODE * H];
__device__ __half h_lg[2][(size_t)NEDGE * H];
__device__ __half h_fn[(size_t)NNODE * H];
__device__ __half h_fe[(size_t)NEDGE * H];
__device__ __half h_fe2[(size_t)NEDGE * H];
__device__ __half h_z[4][(size_t)NEDGE * H];
__device__ __half h_zn[4][(size_t)NNODE * H];
__device__ __half h_out1[(size_t)NEDGE * H];
__device__ __half h_out1n[(size_t)NNODE * H];

// packed fp16 weights (fragment order for mma.m16n8k16)
#define OFFH_WSELF 0
#define OFFH_WKHOP (OFFH_WSELF + 4 * 65536)
#define OFFH_WFUSE (OFFH_WKHOP + 16 * 65536)
#define OFFH_WFF1  (OFFH_WFUSE + 4 * 65536)
#define OFFH_WFF2  (OFFH_WFF1 + 4 * 262144)
#define WBUFH_TOT  (OFFH_WFF2 + 4 * 262144)
__device__ __half g_wbufh[WBUFH_TOT];

// CSR structures
__device__ int g_rp_nd[NNODE + 1];
__device__ int g_ci_nd[NEDGE];
__device__ int g_rp_fn[NNODE + 1];
__device__ int g_ci_fn[2 * NEDGE];
__device__ int g_rp_lg[NEDGE + 1];
__device__ int g_ci_lg[NLG];
__device__ int g_cnt[NEDGE];
__device__ int g_cur[NEDGE];
__device__ int g_bs[1024];
__device__ int g_cnt2[NNODE];
__device__ int g_cur2[NNODE];
__device__ int g_bs2[1024];

__device__ __forceinline__ float gelu_exact(float v) {
    return 0.5f * v * (1.0f + erff(v * 0.70710678118654752f));
}

__device__ __forceinline__ uint32_t pkh2(float a, float b) {
    __half2 h = __floats2half2_rn(a, b);
    return *(uint32_t*)&h;
}
__device__ __forceinline__ float2 uph2(uint32_t u) {
    __half2 h = *(__half2*)&u;
    return __half22float2(h);
}
__device__ __forceinline__ uint32_t pk2(float a, float b) { return pkh2(a, b); }

__device__ __forceinline__ void mma_f16(float* c, const uint32_t* a, const uint32_t* b) {
    asm volatile(
        "mma.sync.aligned.m16n8k16.row.col.f32.f16.f16.f32 "
        "{%0,%1,%2,%3}, {%4,%5,%6,%7}, {%8,%9}, {%0,%1,%2,%3};"
        : "+f"(c[0]), "+f"(c[1]), "+f"(c[2]), "+f"(c[3])
        : "r"(a[0]), "r"(a[1]), "r"(a[2]), "r"(a[3]), "r"(b[0]), "r"(b[1]));
}

// ---------------- CSR build kernels ----------------

__global__ void hist_kernel(const int* __restrict__ key, int* cnt, int n) {
    int i = blockIdx.x * 256 + threadIdx.x;
    if (i < n) atomicAdd(&cnt[__ldg(key + i)], 1);
}

__global__ void scan1_kernel(const int* __restrict__ in, int* __restrict__ out,
                             int* __restrict__ bsums, int n) {
    __shared__ int sh[1024];
    int i = blockIdx.x * 1024 + threadIdx.x;
    int v = (i < n) ? in[i] : 0;
    sh[threadIdx.x] = v;
    __syncthreads();
#pragma unroll
    for (int o = 1; o < 1024; o <<= 1) {
        int t = (threadIdx.x >= o) ? sh[threadIdx.x - o] : 0;
        __syncthreads();
        sh[threadIdx.x] += t;
        __syncthreads();
    }
    if (i < n) out[i] = sh[threadIdx.x] - v;
    if (threadIdx.x == 1023) bsums[blockIdx.x] = sh[1023];
}

__global__ void scan2_kernel(int* bsums, int nb) {
    __shared__ int sh[1024];
    int v = (threadIdx.x < nb) ? bsums[threadIdx.x] : 0;
    sh[threadIdx.x] = v;
    __syncthreads();
#pragma unroll
    for (int o = 1; o < 1024; o <<= 1) {
        int t = (threadIdx.x >= o) ? sh[threadIdx.x - o] : 0;
        __syncthreads();
        sh[threadIdx.x] += t;
        __syncthreads();
    }
    if (threadIdx.x < nb) bsums[threadIdx.x] = sh[threadIdx.x] - v;
}

__global__ void scan3_kernel(int* __restrict__ out, const int* __restrict__ bsums,
                             const int* __restrict__ cnt, int n) {
    int i = blockIdx.x * 1024 + threadIdx.x;
    if (i < n) {
        int v = out[i] + bsums[i >> 10];
        out[i] = v;
        if (i == n - 1) out[n] = v + cnt[i];
    }
}

__global__ void fill_kernel(const int* __restrict__ key, const int* __restrict__ val,
                            int* cursor, int* __restrict__ ci, int n) {
    int i = blockIdx.x * 256 + threadIdx.x;
    if (i >= n) return;
    int pos = atomicAdd(&cursor[__ldg(key + i)], 1);
    ci[pos] = val ? __ldg(val + i) : i;
}

// ---------------- weight pack kernels (f32 -> fp16, m16n8k16 B-fragment order) --------

// H x H (gemm1): per matrix [kt(8)][s(2)][wN(4)][nf4(4)][lane(32)] uint4
__global__ void pack256_kernel(const float* __restrict__ W, __half* __restrict__ out, int nmat) {
    int gid = blockIdx.x * 256 + threadIdx.x;
    if (gid >= nmat * 8192) return;
    int m = gid >> 13, o = gid & 8191;
    int kt = o >> 10, s = (o >> 9) & 1, wN = (o >> 7) & 3, nf4 = (o >> 5) & 3, lane = o & 31;
    int t = lane & 3, g = lane >> 2;
    int k = kt * 32 + s * 16 + 2 * t;
    int n0 = wN * 64 + nf4 * 16 + g, n1 = n0 + 8;
    const float* Wm = W + (size_t)m * 65536;
    uint4 v;
    v.x = pk2(Wm[k * 256 + n0], Wm[(k + 1) * 256 + n0]);
    v.y = pk2(Wm[(k + 8) * 256 + n0], Wm[(k + 9) * 256 + n0]);
    v.z = pk2(Wm[k * 256 + n1], Wm[(k + 1) * 256 + n1]);
    v.w = pk2(Wm[(k + 8) * 256 + n1], Wm[(k + 9) * 256 + n1]);
    ((uint4*)out)[gid] = v;
}

// w_ff1 [256,1024]: per matrix [c(4)][kt(8)][s(2)][wN(8)][nf4(2)][lane] uint4
__global__ void packff1_kernel(const float* __restrict__ W, __half* __restrict__ out, int nmat) {
    int gid = blockIdx.x * 256 + threadIdx.x;
    if (gid >= nmat * 32768) return;
    int m = gid >> 15, o = gid & 32767;
    int c = o >> 13, r = o & 8191;
    int kt = r >> 10, s = (r >> 9) & 1, wN = (r >> 6) & 7, nf4 = (r >> 5) & 1, lane = r & 31;
    int t = lane & 3, g = lane >> 2;
    int k = kt * 32 + s * 16 + 2 * t;
    int n0 = c * 256 + wN * 32 + nf4 * 16 + g, n1 = n0 + 8;
    const float* Wm = W + (size_t)m * 262144;
    uint4 v;
    v.x = pk2(Wm[k * 1024 + n0], Wm[(k + 1) * 1024 + n0]);
    v.y = pk2(Wm[(k + 8) * 1024 + n0], Wm[(k + 9) * 1024 + n0]);
    v.z = pk2(Wm[k * 1024 + n1], Wm[(k + 1) * 1024 + n1]);
    v.w = pk2(Wm[(k + 8) * 1024 + n1], Wm[(k + 9) * 1024 + n1]);
    ((uint4*)out)[gid] = v;
}

// w_ff2 [1024,256]: per matrix [c(4)][kt(8)][s(2)][wN(8)][nf4(2)][lane] uint4
__global__ void packff2_kernel(const float* __restrict__ W, __half* __restrict__ out, int nmat) {
    int gid = blockIdx.x * 256 + threadIdx.x;
    if (gid >= nmat * 32768) return;
    int m = gid >> 15, o = gid & 32767;
    int c = o >> 13, r = o & 8191;
    int kt = r >> 10, s = (r >> 9) & 1, wN = (r >> 6) & 7, nf4 = (r >> 5) & 1, lane = r & 31;
    int t = lane & 3, g = lane >> 2;
    int k = c * 256 + kt * 32 + s * 16 + 2 * t;
    int n0 = wN * 32 + nf4 * 16 + g, n1 = n0 + 8;
    const float* Wm = W + (size_t)m * 262144;
    uint4 v;
    v.x = pk2(Wm[k * 256 + n0], Wm[(k + 1) * 256 + n0]);
    v.y = pk2(Wm[(k + 8) * 256 + n0], Wm[(k + 9) * 256 + n0]);
    v.z = pk2(Wm[k * 256 + n1], Wm[(k + 1) * 256 + n1]);
    v.w = pk2(Wm[(k + 8) * 256 + n1], Wm[(k + 9) * 256 + n1]);
    ((uint4*)out)[gid] = v;
}

// ---------------- small kernels (fp16 activations) ----------------

__global__ void cvth_kernel(const float* __restrict__ in, __half* __restrict__ out, int n8) {
    int i = blockIdx.x * 256 + threadIdx.x;
    if (i >= n8) return;
    const float* p = in + (size_t)i * 8;
    float4 v0 = ((const float4*)p)[0], v1 = ((const float4*)p)[1];
    uint4 o;
    o.x = pk2(v0.x, v0.y); o.y = pk2(v0.z, v0.w);
    o.z = pk2(v1.x, v1.y); o.w = pk2(v1.z, v1.w);
    ((uint4*)out)[i] = o;
}

__global__ void embed_kernel(const float* __restrict__ rel, const int* __restrict__ feat,
                             __half* __restrict__ out) {
    int gid = blockIdx.x * 256 + threadIdx.x;
    int e = gid >> 5;
    if (e >= NEDGE) return;
    int c8 = (gid & 31) * 8;
    int r = __ldg(feat + e);
    const float* p = rel + (size_t)r * H + c8;
    float4 v0 = ((const float4*)p)[0], v1 = ((const float4*)p)[1];
    uint4 o;
    o.x = pk2(v0.x, v0.y); o.y = pk2(v0.z, v0.w);
    o.z = pk2(v1.x, v1.y); o.w = pk2(v1.z, v1.w);
    *(uint4*)(out + (size_t)e * H + c8) = o;
}

__global__ void gather2_kernel(const __half* __restrict__ x, const int* __restrict__ s,
                               const int* __restrict__ d, __half* __restrict__ out, int n) {
    int gid = blockIdx.x * 256 + threadIdx.x;
    int e = gid >> 5;
    if (e >= n) return;
    int c8 = (gid & 31) * 8;
    int si = __ldg(s + e), di = __ldg(d + e);
    uint4 ua = *(const uint4*)(x + (size_t)si * H + c8);
    uint4 ub = *(const uint4*)(x + (size_t)di * H + c8);
    const uint32_t* ap = (const uint32_t*)&ua;
    const uint32_t* bp = (const uint32_t*)&ub;
    uint4 o; uint32_t* op = (uint32_t*)&o;
#pragma unroll
    for (int i = 0; i < 4; i++) {
        float2 fa = uph2(ap[i]), fb = uph2(bp[i]);
        op[i] = pkh2(fa.x + fb.x, fa.y + fb.y);
    }
    *(uint4*)(out + (size_t)e * H + c8) = o;
}

// CSR gather segment-sum, fp16 in/out, f32 accumulate, 4-way unrolled
__global__ void segsum_kernel(const __half* __restrict__ rows, const int* __restrict__ rp,
                              const int* __restrict__ ci, __half* __restrict__ out, int nseg) {
    int row = blockIdx.x * 8 + (threadIdx.x >> 5);
    if (row >= nseg) return;
    int lane = threadIdx.x & 31;
    int beg = __ldg(rp + row), end = __ldg(rp + row + 1);
    float a[8] = {0.f,0.f,0.f,0.f,0.f,0.f,0.f,0.f};
    float b[8] = {0.f,0.f,0.f,0.f,0.f,0.f,0.f,0.f};
    int j = beg;
    for (; j + 3 < end; j += 4) {
        uint4 u0 = *(const uint4*)(rows + (size_t)__ldg(ci + j)     * H + lane * 8);
        uint4 u1 = *(const uint4*)(rows + (size_t)__ldg(ci + j + 1) * H + lane * 8);
        uint4 u2 = *(const uint4*)(rows + (size_t)__ldg(ci + j + 2) * H + lane * 8);
        uint4 u3 = *(const uint4*)(rows + (size_t)__ldg(ci + j + 3) * H + lane * 8);
        const uint32_t* p0 = (const uint32_t*)&u0;
        const uint32_t* p1 = (const uint32_t*)&u1;
        const uint32_t* p2 = (const uint32_t*)&u2;
        const uint32_t* p3 = (const uint32_t*)&u3;
#pragma unroll
        for (int i = 0; i < 4; i++) {
            float2 f0 = uph2(p0[i]); a[2*i] += f0.x; a[2*i+1] += f0.y;
            float2 f1 = uph2(p1[i]); b[2*i] += f1.x; b[2*i+1] += f1.y;
            float2 f2 = uph2(p2[i]); a[2*i] += f2.x; a[2*i+1] += f2.y;
            float2 f3 = uph2(p3[i]); b[2*i] += f3.x; b[2*i+1] += f3.y;
        }
    }
    for (; j < end; j++) {
        uint4 u = *(const uint4*)(rows + (size_t)__ldg(ci + j) * H + lane * 8);
        const uint32_t* up = (const uint32_t*)&u;
#pragma unroll
        for (int i = 0; i < 4; i++) {
            float2 f = uph2(up[i]); a[2*i] += f.x; a[2*i+1] += f.y;
        }
    }
    uint4 o; uint32_t* op = (uint32_t*)&o;
#pragma unroll
    for (int i = 0; i < 4; i++) op[i] = pkh2(a[2*i] + b[2*i], a[2*i+1] + b[2*i+1]);
    *(uint4*)(out + (size_t)row * H + lane * 8) = o;
}

__global__ void segsum_rel_kernel(const float* __restrict__ rel, const int* __restrict__ feat,
                                  const int* __restrict__ rp, const int* __restrict__ ci,
                                  __half* __restrict__ out, int nseg) {
    int row = blockIdx.x * 8 + (threadIdx.x >> 5);
    if (row >= nseg) return;
    int lane = threadIdx.x & 31;
    int beg = __ldg(rp + row), end = __ldg(rp + row + 1);
    float a[8] = {0.f,0.f,0.f,0.f,0.f,0.f,0.f,0.f};
    for (int j = beg; j < end; j++) {
        int r = __ldg(feat + __ldg(ci + j));
        const float* p = rel + (size_t)r * H + lane * 8;
        float4 v0 = ((const float4*)p)[0], v1 = ((const float4*)p)[1];
        float2 q;
        q = uph2(pk2(v0.x, v0.y)); a[0] += q.x; a[1] += q.y;
        q = uph2(pk2(v0.z, v0.w)); a[2] += q.x; a[3] += q.y;
        q = uph2(pk2(v1.x, v1.y)); a[4] += q.x; a[5] += q.y;
        q = uph2(pk2(v1.z, v1.w)); a[6] += q.x; a[7] += q.y;
    }
    uint4 o; uint32_t* op = (uint32_t*)&o;
#pragma unroll
    for (int i = 0; i < 4; i++) op[i] = pkh2(a[2*i], a[2*i+1]);
    *(uint4*)(out + (size_t)row * H + lane * 8) = o;
}

// ================= GEMM1 + LN1 fused (fp16), BM=128, 512 threads =================
// warps: 4 along M (m32) x 4 along N (n64); residual read from gmem in epilogue.
#define G1_SMEM_BYTES (20480 + 32768 + 7168)   // A 2x5120h, B 2x8192h, f32 tables

struct G1Args {
    const __half* A[6];
    const __half* W[6];
    const float* Bias[6];
    const __half* xres;
    const float* gamma;
    const float* beta;
};

__global__ void __launch_bounds__(512, 1)
gemm1_ln_kernel(G1Args args, int M, __half* __restrict__ out) {
    extern __shared__ char smraw[];
    __half* As = (__half*)smraw;                // 2 x 5120 halves (stride 40)
    __half* Bs = As + 2 * 5120;                 // 2 x 8192 halves
    float* bias_s = (float*)(Bs + 2 * 8192);
    float* gs  = bias_s + 256;
    float* bt  = gs + 256;
    float* lnS = bt + 256;                      // 512
    float* lnQ = lnS + 512;                     // 512

    int tid = threadIdx.x;
    int bm = blockIdx.x * 128;
    if (tid < 256) {
        float b = 0.f;
#pragma unroll
        for (int j = 0; j < 6; j++) b += __ldg(args.Bias[j] + tid);
        bias_s[tid] = b;
        gs[tid] = __ldg(args.gamma + tid);
        bt[tid] = __ldg(args.beta + tid);
    }

    uint32_t sbase = (uint32_t)__cvta_generic_to_shared(smraw);
    uint32_t a_base = sbase;
    uint32_t b_base = sbase + 20480;

    int warp = tid >> 5, lane = tid & 31, g = lane >> 2, t = lane & 3;
    int wm = (warp >> 2) * 32;    // 4 m-warps
    int wN = warp & 3;            // 4 n-warps
    int wn = wN * 64;

    float acc[2][8][4];
#pragma unroll
    for (int mt = 0; mt < 2; mt++)
#pragma unroll
        for (int nf = 0; nf < 8; nf++)
#pragma unroll
            for (int i = 0; i < 4; i++) acc[mt][nf][i] = 0.f;

    auto issue = [&](int tt, int buf) {
        int j = tt >> 3, kt = tt & 7;
        const __half* A = args.A[j];
        const uint4* Wp = (const uint4*)args.W[j] + (size_t)kt * 1024;
        {
            int r = tid >> 2, cp = tid & 3;      // 128 rows x 4 chunks of 16B
            int row = bm + r;
            uint32_t dst = a_base + (uint32_t)(buf * 10240 + r * 80 + cp * 16);
            const __half* src = A + (size_t)row * H + kt * 32 + cp * 8;
            int sz = (row < M) ? 16 : 0;
            asm volatile("cp.async.cg.shared.global [%0], [%1], 16, %2;\n"
                         :: "r"(dst), "l"(src), "r"(sz));
        }
#pragma unroll
        for (int i = 0; i < 2; i++) {
            int idx = tid + i * 512;
            uint32_t dst = b_base + (uint32_t)(buf * 16384 + idx * 16);
            asm volatile("cp.async.cg.shared.global [%0], [%1], 16;\n"
                         :: "r"(dst), "l"(Wp + idx));
        }
        asm volatile("cp.async.commit_group;\n");
    };

    issue(0, 0);
    for (int tt = 0; tt < 48; tt++) {
        asm volatile("cp.async.wait_group 0;\n");
        __syncthreads();
        if (tt + 1 < 48) issue(tt + 1, (tt + 1) & 1);
        const __half* Ab = As + (tt & 1) * 5120;
        const uint4* Bb4 = (const uint4*)(Bs + (tt & 1) * 8192) + wN * 128 + lane;
#pragma unroll
        for (int s = 0; s < 2; s++) {
            int k0 = s * 16 + 2 * t;
            const __half* Ar0 = Ab + (wm + g) * 40 + k0;
            const __half* Ar1 = Ab + (wm + 8 + g) * 40 + k0;
            const __half* Ar2 = Ab + (wm + 16 + g) * 40 + k0;
            const __half* Ar3 = Ab + (wm + 24 + g) * 40 + k0;
            uint32_t a0[4], a1[4];
            a0[0] = *(const uint32_t*)Ar0;
            a0[1] = *(const uint32_t*)Ar1;
            a0[2] = *(const uint32_t*)(Ar0 + 8);
            a0[3] = *(const uint32_t*)(Ar1 + 8);
            a1[0] = *(const uint32_t*)Ar2;
            a1[1] = *(const uint32_t*)Ar3;
            a1[2] = *(const uint32_t*)(Ar2 + 8);
            a1[3] = *(const uint32_t*)(Ar3 + 8);
#pragma unroll
            for (int nf4 = 0; nf4 < 4; nf4++) {
                uint4 bv = Bb4[s * 512 + nf4 * 32];
                uint32_t b0[2] = {bv.x, bv.y};
                uint32_t b1[2] = {bv.z, bv.w};
                mma_f16(acc[0][2 * nf4], a0, b0);
                mma_f16(acc[1][2 * nf4], a1, b0);
                mma_f16(acc[0][2 * nf4 + 1], a0, b1);
                mma_f16(acc[1][2 * nf4 + 1], a1, b1);
            }
        }
    }

    // bias+gelu+residual (residual straight from gmem; L2-hot), per-row partials
#pragma unroll
    for (int mt = 0; mt < 2; mt++) {
#pragma unroll
        for (int h = 0; h < 2; h++) {
            int row = wm + mt * 16 + h * 8 + g;
            bool ok = (bm + row) < M;
            const __half* xr = args.xres + (size_t)(bm + row) * H;
            float s = 0.f, q = 0.f;
#pragma unroll
            for (int nf = 0; nf < 8; nf++) {
                int col = wn + nf * 8 + 2 * t;
                float2 xv = make_float2(0.f, 0.f);
                if (ok) xv = uph2(__ldg((const uint32_t*)(xr + col)));
                float v0 = xv.x + gelu_exact(acc[mt][nf][2 * h]     + bias_s[col]);
                float v1 = xv.y + gelu_exact(acc[mt][nf][2 * h + 1] + bias_s[col + 1]);
                acc[mt][nf][2 * h] = v0; acc[mt][nf][2 * h + 1] = v1;
                s += v0 + v1; q += v0 * v0 + v1 * v1;
            }
#pragma unroll
            for (int o = 1; o <= 2; o <<= 1) {
                s += __shfl_xor_sync(0xffffffffu, s, o);
                q += __shfl_xor_sync(0xffffffffu, q, o);
            }
            if (t == 0) { lnS[row * 4 + wN] = s; lnQ[row * 4 + wN] = q; }
        }
    }
    __syncthreads();
#pragma unroll
    for (int mt = 0; mt < 2; mt++) {
#pragma unroll
        for (int h = 0; h < 2; h++) {
            int row = wm + mt * 16 + h * 8 + g;
            float S = lnS[row * 4] + lnS[row * 4 + 1] + lnS[row * 4 + 2] + lnS[row * 4 + 3];
            float Q = lnQ[row * 4] + lnQ[row * 4 + 1] + lnQ[row * 4 + 2] + lnQ[row * 4 + 3];
            float m = S * (1.f / H), v = Q * (1.f / H) - m * m, rs = rsqrtf(v + 1e-5f);
            if (bm + row < M) {
#pragma unroll
                for (int nf = 0; nf < 8; nf++) {
                    int col = wn + nf * 8 + 2 * t;
                    float o0 = (acc[mt][nf][2 * h]     - m) * rs * gs[col]     + bt[col];
                    float o1 = (acc[mt][nf][2 * h + 1] - m) * rs * gs[col + 1] + bt[col + 1];
                    *(uint32_t*)(out + (size_t)(bm + row) * H + col) = pkh2(o0, o1);
                }
            }
        }
    }
}

// ================= fused FFN + LN2 (fp16), 4 chunks of 256, mW=2 x nW=8 =============
#define F_SMEM_BYTES (33792 + 33792 + 32768 + 8192)   // 108544

struct FArgs {
    const __half* w1;
    const float* b1;
    const __half* w2;
    const float* b2;
    const float* gamma;
    const float* beta;
};

__global__ void __launch_bounds__(512, 1)
ffn_kernel(FArgs args, int M, const __half* __restrict__ in1,
           void* __restrict__ outv, int out_half) {
    extern __shared__ char smraw[];
    __half* xs  = (__half*)smraw;            // 64 x 264 halves
    __half* hb  = xs + 64 * 264;             // 64 x 264 halves (256 used)
    __half* Bst = hb + 64 * 264;             // 2 x 8192 halves
    float* b2s = (float*)(Bst + 2 * 8192);
    float* gs  = b2s + 256;
    float* bt  = gs + 256;
    float* b1c = bt + 256;
    float* lnS = b1c + 256;
    float* lnQ = lnS + 512;

    int tid = threadIdx.x;
    int bm = blockIdx.x * 64;

    if (tid < 256) {
        b2s[tid] = __ldg(args.b2 + tid);
        gs[tid]  = __ldg(args.gamma + tid);
        bt[tid]  = __ldg(args.beta + tid);
    }
#pragma unroll
    for (int i = 0; i < 4; i++) {
        int idx = tid + i * 512;
        int r = idx >> 5, c8 = (idx & 31) * 8;
        int row = bm + r;
        uint4 v = make_uint4(0, 0, 0, 0);
        if (row < M) v = *(const uint4*)(in1 + (size_t)row * H + c8);
        *(uint4*)(xs + r * 264 + c8) = v;
    }

    uint32_t bst_base = (uint32_t)__cvta_generic_to_shared(Bst);
    int warp = tid >> 5, lane = tid & 31, g = lane >> 2, t = lane & 3;
    int wm = (warp >> 3) * 32;
    int wN = warp & 7;
    int wn = wN * 32;

    float acc2[2][4][4];
#pragma unroll
    for (int mt = 0; mt < 2; mt++)
#pragma unroll
        for (int nf = 0; nf < 4; nf++)
#pragma unroll
            for (int i = 0; i < 4; i++) acc2[mt][nf][i] = 0.f;

    __syncthreads();

    for (int c = 0; c < 4; c++) {
        if (c > 0) __syncthreads();
        if (tid < 256) b1c[tid] = __ldg(args.b1 + c * 256 + tid);

        float acc1[2][4][4];
#pragma unroll
        for (int mt = 0; mt < 2; mt++)
#pragma unroll
            for (int nf = 0; nf < 4; nf++)
#pragma unroll
                for (int i = 0; i < 4; i++) acc1[mt][nf][i] = 0.f;

        const uint4* W1p = (const uint4*)args.w1 + (size_t)c * 8192;
        auto issue1 = [&](int kt, int buf) {
#pragma unroll
            for (int i = 0; i < 2; i++) {
                int idx = tid + i * 512;
                uint32_t dst = bst_base + (uint32_t)(buf * 16384 + idx * 16);
                asm volatile("cp.async.cg.shared.global [%0], [%1], 16;\n"
                             :: "r"(dst), "l"(W1p + kt * 1024 + idx));
            }
            asm volatile("cp.async.commit_group;\n");
        };

        issue1(0, 0);
        for (int kt = 0; kt < 8; kt++) {
            asm volatile("cp.async.wait_group 0;\n");
            __syncthreads();
            if (kt + 1 < 8) issue1(kt + 1, (kt + 1) & 1);
            const uint4* Bb4 = (const uint4*)(Bst + (kt & 1) * 8192) + wN * 64 + lane;
#pragma unroll
            for (int s = 0; s < 2; s++) {
                int kg = kt * 32 + s * 16 + 2 * t;
                const __half* Ar0 = xs + (wm + g) * 264 + kg;
                const __half* Ar1 = xs + (wm + 8 + g) * 264 + kg;
                const __half* Ar2 = xs + (wm + 16 + g) * 264 + kg;
                const __half* Ar3 = xs + (wm + 24 + g) * 264 + kg;
                uint32_t a0[4], a1[4];
                a0[0] = *(const uint32_t*)Ar0;
                a0[1] = *(const uint32_t*)Ar1;
                a0[2] = *(const uint32_t*)(Ar0 + 8);
                a0[3] = *(const uint32_t*)(Ar1 + 8);
                a1[0] = *(const uint32_t*)Ar2;
                a1[1] = *(const uint32_t*)Ar3;
                a1[2] = *(const uint32_t*)(Ar2 + 8);
                a1[3] = *(const uint32_t*)(Ar3 + 8);
#pragma unroll
                for (int nf4 = 0; nf4 < 2; nf4++) {
                    uint4 bv = Bb4[s * 512 + nf4 * 32];
                    uint32_t b0[2] = {bv.x, bv.y};
                    uint32_t b1[2] = {bv.z, bv.w};
                    mma_f16(acc1[0][2 * nf4], a0, b0);
                    mma_f16(acc1[1][2 * nf4], a1, b0);
                    mma_f16(acc1[0][2 * nf4 + 1], a0, b1);
                    mma_f16(acc1[1][2 * nf4 + 1], a1, b1);
                }
            }
        }

#pragma unroll
        for (int mt = 0; mt < 2; mt++) {
#pragma unroll
            for (int nf = 0; nf < 4; nf++) {
                int col = wn + nf * 8 + 2 * t;
                float h0 = gelu_exact(acc1[mt][nf][0] + b1c[col]);
                float h1 = gelu_exact(acc1[mt][nf][1] + b1c[col + 1]);
                float h2v = gelu_exact(acc1[mt][nf][2] + b1c[col]);
                float h3v = gelu_exact(acc1[mt][nf][3] + b1c[col + 1]);
                *(uint32_t*)(hb + (wm + mt * 16 + g) * 264 + col)     = pkh2(h0, h1);
                *(uint32_t*)(hb + (wm + mt * 16 + 8 + g) * 264 + col) = pkh2(h2v, h3v);
            }
        }
        __syncthreads();

        const uint4* W2p = (const uint4*)args.w2 + (size_t)c * 8192;
        auto issue2 = [&](int kt, int buf) {
#pragma unroll
            for (int i = 0; i < 2; i++) {
                int idx = tid + i * 512;
                uint32_t dst = bst_base + (uint32_t)(buf * 16384 + idx * 16);
                asm volatile("cp.async.cg.shared.global [%0], [%1], 16;\n"
                             :: "r"(dst), "l"(W2p + kt * 1024 + idx));
            }
            asm volatile("cp.async.commit_group;\n");
        };

        issue2(0, 0);
        for (int kt = 0; kt < 8; kt++) {
            asm volatile("cp.async.wait_group 0;\n");
            __syncthreads();
            if (kt + 1 < 8) issue2(kt + 1, (kt + 1) & 1);
            const uint4* Bb4 = (const uint4*)(Bst + (kt & 1) * 8192) + wN * 64 + lane;
#pragma unroll
            for (int s = 0; s < 2; s++) {
                int kg = kt * 32 + s * 16 + 2 * t;
                const __half* Ar0 = hb + (wm + g) * 264 + kg;
                const __half* Ar1 = hb + (wm + 8 + g) * 264 + kg;
                const __half* Ar2 = hb + (wm + 16 + g) * 264 + kg;
                const __half* Ar3 = hb + (wm + 24 + g) * 264 + kg;
                uint32_t a0[4], a1[4];
                a0[0] = *(const uint32_t*)Ar0;
                a0[1] = *(const uint32_t*)Ar1;
                a0[2] = *(const uint32_t*)(Ar0 + 8);
                a0[3] = *(const uint32_t*)(Ar1 + 8);
                a1[0] = *(const uint32_t*)Ar2;
                a1[1] = *(const uint32_t*)Ar3;
                a1[2] = *(const uint32_t*)(Ar2 + 8);
                a1[3] = *(const uint32_t*)(Ar3 + 8);
#pragma unroll
                for (int nf4 = 0; nf4 < 2; nf4++) {
                    uint4 bv = Bb4[s * 512 + nf4 * 32];
                    uint32_t b0[2] = {bv.x, bv.y};
                    uint32_t b1[2] = {bv.z, bv.w};
                    mma_f16(acc2[0][2 * nf4], a0, b0);
                    mma_f16(acc2[1][2 * nf4], a1, b0);
                    mma_f16(acc2[0][2 * nf4 + 1], a0, b1);
                    mma_f16(acc2[1][2 * nf4 + 1], a1, b1);
                }
            }
        }
    }

    // LN2 epilogue
#pragma unroll
    for (int mt = 0; mt < 2; mt++) {
#pragma unroll
        for (int h = 0; h < 2; h++) {
            int row = wm + mt * 16 + h * 8 + g;
            float s = 0.f, q = 0.f;
#pragma unroll
            for (int nf = 0; nf < 4; nf++) {
                int col = wn + nf * 8 + 2 * t;
                float2 xv = uph2(*(const uint32_t*)(xs + row * 264 + col));
                float v0 = xv.x + acc2[mt][nf][2 * h]     + b2s[col];
                float v1 = xv.y + acc2[mt][nf][2 * h + 1] + b2s[col + 1];
                acc2[mt][nf][2 * h] = v0; acc2[mt][nf][2 * h + 1] = v1;
                s += v0 + v1; q += v0 * v0 + v1 * v1;
            }
#pragma unroll
            for (int o = 1; o <= 2; o <<= 1) {
                s += __shfl_xor_sync(0xffffffffu, s, o);
                q += __shfl_xor_sync(0xffffffffu, q, o);
            }
            if (t == 0) { lnS[row * 8 + wN] = s; lnQ[row * 8 + wN] = q; }
        }
    }
    __syncthreads();
#pragma unroll
    for (int mt = 0; mt < 2; mt++) {
#pragma unroll
        for (int h = 0; h < 2; h++) {
            int row = wm + mt * 16 + h * 8 + g;
            float S = 0.f, Q = 0.f;
#pragma unroll
            for (int i = 0; i < 8; i++) { S += lnS[row * 8 + i]; Q += lnQ[row * 8 + i]; }
            float m = S * (1.f / H), v = Q * (1.f / H) - m * m, rs = rsqrtf(v + 1e-5f);
            if (bm + row < M) {
#pragma unroll
                for (int nf = 0; nf < 4; nf++) {
                    int col = wn + nf * 8 + 2 * t;
                    float o0 = (acc2[mt][nf][2 * h]     - m) * rs * gs[col]     + bt[col];
                    float o1 = (acc2[mt][nf][2 * h + 1] - m) * rs * gs[col + 1] + bt[col + 1];
                    if (out_half) {
                        *(uint32_t*)((__half*)outv + (size_t)(bm + row) * H + col) = pkh2(o0, o1);
                    } else {
                        *(float2*)((float*)outv + (size_t)(bm + row) * H + col) = make_float2(o0, o1);
                    }
                }
            }
        }
    }
}

// ---------------- host orchestration ----------------

struct Net {
    const float *b_self, *b_khop, *b_fuse, *b_ff1, *b_ff2;
    const float *ln1g, *ln1b, *ln2g, *ln2b;
    __half* wbuf;
};

static void run_core(const Net& n, int l, int c, int M, __half* const* z,
                     const __half* xin, const __half* fused, __half* out1buf,
                     void* outp, int out_half, cudaStream_t st) {
    size_t lc = (size_t)(l * 2 + c);
    G1Args ga;
    ga.A[0] = xin;
    ga.W[0] = n.wbuf + OFFH_WSELF + lc * 65536;
    ga.Bias[0] = n.b_self + lc * H;
    for (int i = 0; i < 4; i++) {
        ga.A[1 + i] = z[i];
        ga.W[1 + i] = n.wbuf + OFFH_WKHOP + (lc * 4 + i) * (size_t)65536;
        ga.Bias[1 + i] = n.b_khop + (lc * 4 + i) * (size_t)H;
    }
    ga.A[5] = fused;
    ga.W[5] = n.wbuf + OFFH_WFUSE + lc * 65536;
    ga.Bias[5] = n.b_fuse + lc * H;
    ga.xres = xin;
    ga.gamma = n.ln1g + lc * H;
    ga.beta  = n.ln1b + lc * H;

    gemm1_ln_kernel<<<(M + 127) / 128, 512, G1_SMEM_BYTES, st>>>(ga, M, out1buf);

    FArgs fa;
    fa.w1 = n.wbuf + OFFH_WFF1 + lc * (size_t)262144;
    fa.b1 = n.b_ff1 + lc * FH;
    fa.w2 = n.wbuf + OFFH_WFF2 + lc * (size_t)262144;
    fa.b2 = n.b_ff2 + lc * H;
    fa.gamma = n.ln2g + lc * H;
    fa.beta  = n.ln2b + lc * H;
    ffn_kernel<<<(M + 63) / 64, 512, F_SMEM_BYTES, st>>>(fa, M, out1buf, outp, out_half);
}

static void exclusive_scan(int* cnt, int* rp, int* bsums, int n, cudaStream_t st) {
    int nb = (n + 1023) / 1024;
    scan1_kernel<<<nb, 1024, 0, st>>>(cnt, rp, bsums, n);
    scan2_kernel<<<1, 1024, 0, st>>>(bsums, nb);
    scan3_kernel<<<nb, 1024, 0, st>>>(rp, bsums, cnt, n);
}

extern "C" void kernel_launch(void* const* d_in, const int* in_sizes, int n_in,
                              void* d_out, int out_size) {
    const float* x_in = (const float*)d_in[0];
    const int* feat   = (const int*)d_in[1];
    const int* eig    = (const int*)d_in[2];
    const int* eil    = (const int*)d_in[3];
    const float* rel  = (const float*)d_in[4];

    const float* w_self = (const float*)d_in[5];
    const float* w_khop = (const float*)d_in[7];
    const float* w_fuse = (const float*)d_in[9];
    const float* w_ff1  = (const float*)d_in[11];
    const float* w_ff2  = (const float*)d_in[13];

    Net n;
    n.b_self = (const float*)d_in[6];
    n.b_khop = (const float*)d_in[8];
    n.b_fuse = (const float*)d_in[10];
    n.b_ff1  = (const float*)d_in[12];
    n.b_ff2  = (const float*)d_in[14];
    n.ln1g   = (const float*)d_in[15]; n.ln1b = (const float*)d_in[16];
    n.ln2g   = (const float*)d_in[17]; n.ln2b = (const float*)d_in[18];

    cudaFuncSetAttribute(gemm1_ln_kernel,
                         cudaFuncAttributeMaxDynamicSharedMemorySize, G1_SMEM_BYTES);
    cudaFuncSetAttribute(ffn_kernel,
                         cudaFuncAttributeMaxDynamicSharedMemorySize, F_SMEM_BYTES);

    static cudaStream_t s2 = nullptr;
    static cudaEvent_t ev_start, ev_prep, ev_x0, ev_lg0, ev_fin;
    if (!s2) {
        cudaStreamCreateWithFlags(&s2, cudaStreamNonBlocking);
        cudaEventCreateWithFlags(&ev_start, cudaEventDisableTiming);
        cudaEventCreateWithFlags(&ev_prep,  cudaEventDisableTiming);
        cudaEventCreateWithFlags(&ev_x0,    cudaEventDisableTiming);
        cudaEventCreateWithFlags(&ev_lg0,   cudaEventDisableTiming);
        cudaEventCreateWithFlags(&ev_fin,   cudaEventDisableTiming);
    }

    __half *px0, *plg0, *pfn, *pfe, *pfe2, *pzbase, *pznb, *pout1, *pout1n, *pwbuf;
    int *rp_nd, *ci_nd, *rp_fn, *ci_fn, *rp_lg, *ci_lg;
    int *pcnt, *pcur, *pbs, *pcnt2, *pcur2, *pbs2;
    cudaGetSymbolAddress((void**)&px0,   h_x);
    cudaGetSymbolAddress((void**)&plg0,  h_lg);
    cudaGetSymbolAddress((void**)&pfn,   h_fn);
    cudaGetSymbolAddress((void**)&pfe,   h_fe);
    cudaGetSymbolAddress((void**)&pfe2,  h_fe2);
    cudaGetSymbolAddress((void**)&pzbase,h_z);
    cudaGetSymbolAddress((void**)&pznb,  h_zn);
    cudaGetSymbolAddress((void**)&pout1, h_out1);
    cudaGetSymbolAddress((void**)&pout1n,h_out1n);
    cudaGetSymbolAddress((void**)&pwbuf, g_wbufh);
    cudaGetSymbolAddress((void**)&rp_nd, g_rp_nd);
    cudaGetSymbolAddress((void**)&ci_nd, g_ci_nd);
    cudaGetSymbolAddress((void**)&rp_fn, g_rp_fn);
    cudaGetSymbolAddress((void**)&ci_fn, g_ci_fn);
    cudaGetSymbolAddress((void**)&rp_lg, g_rp_lg);
    cudaGetSymbolAddress((void**)&ci_lg, g_ci_lg);
    cudaGetSymbolAddress((void**)&pcnt,  g_cnt);
    cudaGetSymbolAddress((void**)&pcur,  g_cur);
    cudaGetSymbolAddress((void**)&pbs,   g_bs);
    cudaGetSymbolAddress((void**)&pcnt2, g_cnt2);
    cudaGetSymbolAddress((void**)&pcur2, g_cur2);
    cudaGetSymbolAddress((void**)&pbs2,  g_bs2);

    n.wbuf = pwbuf;
    __half* px[2]  = {px0,  px0  + (size_t)NNODE * H};
    __half* plg[2] = {plg0, plg0 + (size_t)NEDGE * H};
    __half* ze[4]; __half* zn[4];
    for (int i = 0; i < 4; i++) {
        ze[i] = pzbase + (size_t)i * NEDGE * H;
        zn[i] = pznb + (size_t)i * NNODE * H;
    }

    const int* src_g = eig;  const int* dst_g = eig + NEDGE;
    const int* src_l = eil;  const int* dst_l = eil + NLG;

    // fork point for capture (s2 depends only on this)
    cudaEventRecord(ev_start, 0);
    cudaStreamWaitEvent(s2, ev_start, 0);

    // ===== stream 0 FIRST (so ncu -s 5 lands on the hot CSR/hop path): lg CSR + hops l0 =====
    cudaMemsetAsync(pcnt, 0, NEDGE * sizeof(int), 0);
    hist_kernel<<<(NLG + 255) / 256, 256>>>(dst_l, pcnt, NLG);
    exclusive_scan(pcnt, rp_lg, pbs, NEDGE, 0);
    cudaMemcpyAsync(pcur, rp_lg, NEDGE * sizeof(int), cudaMemcpyDeviceToDevice, 0);
    fill_kernel<<<(NLG + 255) / 256, 256>>>(dst_l, src_l, pcur, ci_lg, NLG);

    segsum_rel_kernel<<<(NEDGE + 7) / 8, 256>>>(rel, feat, rp_lg, ci_lg, ze[0], NEDGE);
    segsum_kernel<<<(NEDGE + 7) / 8, 256>>>(ze[0], rp_lg, ci_lg, ze[1], NEDGE);
    segsum_kernel<<<(NEDGE + 7) / 8, 256>>>(ze[1], rp_lg, ci_lg, ze[2], NEDGE);
    segsum_kernel<<<(NEDGE + 7) / 8, 256>>>(ze[2], rp_lg, ci_lg, ze[3], NEDGE);

    // ===== stream s2: packs + init + gather2-l0 =====
    cvth_kernel<<<(NNODE * H / 8 + 255) / 256, 256, 0, s2>>>(x_in, px[0], NNODE * H / 8);
    embed_kernel<<<NEDGE * 32 / 256, 256, 0, s2>>>(rel, feat, plg[0]);
    pack256_kernel<<<(4 * 8192 + 255) / 256, 256, 0, s2>>>(w_self, pwbuf + OFFH_WSELF, 4);
    pack256_kernel<<<(16 * 8192 + 255) / 256, 256, 0, s2>>>(w_khop, pwbuf + OFFH_WKHOP, 16);
    pack256_kernel<<<(4 * 8192 + 255) / 256, 256, 0, s2>>>(w_fuse, pwbuf + OFFH_WFUSE, 4);
    packff1_kernel<<<(4 * 32768 + 255) / 256, 256, 0, s2>>>(w_ff1, pwbuf + OFFH_WFF1, 4);
    packff2_kernel<<<(4 * 32768 + 255) / 256, 256, 0, s2>>>(w_ff2, pwbuf + OFFH_WFF2, 4);
    gather2_kernel<<<NEDGE * 32 / 256, 256, 0, s2>>>(px[0], src_g, dst_g, pfe, NEDGE);
    cudaEventRecord(ev_prep, s2);

    // ===== stream s2: node CSRs + node core layer 0 =====
    cudaMemsetAsync(pcnt2, 0, NNODE * sizeof(int), s2);
    hist_kernel<<<(NEDGE + 255) / 256, 256, 0, s2>>>(dst_g, pcnt2, NEDGE);
    exclusive_scan(pcnt2, rp_nd, pbs2, NNODE, s2);
    cudaMemcpyAsync(pcur2, rp_nd, NNODE * sizeof(int), cudaMemcpyDeviceToDevice, s2);
    fill_kernel<<<(NEDGE + 255) / 256, 256, 0, s2>>>(dst_g, src_g, pcur2, ci_nd, NEDGE);

    cudaMemsetAsync(pcnt2, 0, NNODE * sizeof(int), s2);
    hist_kernel<<<(NEDGE + 255) / 256, 256, 0, s2>>>(src_g, pcnt2, NEDGE);
    hist_kernel<<<(NEDGE + 255) / 256, 256, 0, s2>>>(dst_g, pcnt2, NEDGE);
    exclusive_scan(pcnt2, rp_fn, pbs2, NNODE, s2);
    cudaMemcpyAsync(pcur2, rp_fn, NNODE * sizeof(int), cudaMemcpyDeviceToDevice, s2);
    fill_kernel<<<(NEDGE + 255) / 256, 256, 0, s2>>>(src_g, nullptr, pcur2, ci_fn, NEDGE);
    fill_kernel<<<(NEDGE + 255) / 256, 256, 0, s2>>>(dst_g, nullptr, pcur2, ci_fn, NEDGE);

    segsum_kernel<<<(NNODE + 7) / 8, 256, 0, s2>>>(plg[0], rp_fn, ci_fn, pfn, NNODE);
    {
        const __half* prev = px[0];
        for (int i = 0; i < 4; i++) {
            segsum_kernel<<<(NNODE + 7) / 8, 256, 0, s2>>>(prev, rp_nd, ci_nd, zn[i], NNODE);
            prev = zn[i];
        }
    }
    run_core(n, 0, 0, NNODE, zn, px[0], pfn, pout1n, px[1], 1, s2);
    gather2_kernel<<<NEDGE * 32 / 256, 256, 0, s2>>>(px[1], src_g, dst_g, pfe2, NEDGE);
    cudaEventRecord(ev_x0, s2);

    // ===== stream 0: edge core, layer 0 =====
    cudaStreamWaitEvent(0, ev_prep, 0);
    run_core(n, 0, 1, NEDGE, ze, plg[0], pfe, pout1, plg[1], 1, (cudaStream_t)0);
    cudaEventRecord(ev_lg0, 0);

    // ===== stream s2: node core, layer 1 =====
    cudaStreamWaitEvent(s2, ev_lg0, 0);
    segsum_kernel<<<(NNODE + 7) / 8, 256, 0, s2>>>(plg[1], rp_fn, ci_fn, pfn, NNODE);
    {
        const __half* prev = px[1];
        for (int i = 0; i < 4; i++) {
            segsum_kernel<<<(NNODE + 7) / 8, 256, 0, s2>>>(prev, rp_nd, ci_nd, zn[i], NNODE);
            prev = zn[i];
        }
    }
    run_core(n, 1, 0, NNODE, zn, px[1], pfn, pout1n, (float*)d_out, 0, s2);
    cudaEventRecord(ev_fin, s2);

    // ===== stream 0: edge core, layer 1 =====
    {
        const __half* prev = plg[1];
        for (int i = 0; i < 4; i++) {
            segsum_kernel<<<(NEDGE + 7) / 8, 256>>>(prev, rp_lg, ci_lg, ze[i], NEDGE);
            prev = ze[i];
        }
    }
    cudaStreamWaitEvent(0, ev_x0, 0);
    run_core(n, 1, 1, NEDGE, ze, plg[1], pfe2, pout1,
             (float*)d_out + (size_t)NNODE * H, 0, (cudaStream_t)0);

    cudaStreamWaitEvent(0, ev_fin, 0);
    (void)in_sizes; (void)n_in; (void)out_size;
}

// round 14
// speedup vs baseline: 1.0513x; 1.0513x over previous
#include <cuda_runtime.h>
#include <cuda_fp16.h>
#include <cstdint>
#include <math.h>

#define H       256
#define FH      1024
#define NNODE   20000
#define NEDGE   160000
#define NLG     640000

// ---------------- scratch (static device memory; no allocations) ----------------
__device__ __half h_x[2][(size_t)NNODE * H];
__device__ __half h_lg[2][(size_t)NEDGE * H];
__device__ __half h_fn[(size_t)NNODE * H];
__device__ __half h_fe[(size_t)NEDGE * H];
__device__ __half h_fe2[(size_t)NEDGE * H];
__device__ __half h_z[4][(size_t)NEDGE * H];
__device__ __half h_zn[4][(size_t)NNODE * H];
__device__ __half h_out1[(size_t)NEDGE * H];
__device__ __half h_out1n[(size_t)NNODE * H];

// packed fp16 weights (fragment order for mma.m16n8k16)
#define OFFH_WSELF 0
#define OFFH_WKHOP (OFFH_WSELF + 4 * 65536)
#define OFFH_WFUSE (OFFH_WKHOP + 16 * 65536)
#define OFFH_WFF1  (OFFH_WFUSE + 4 * 65536)
#define OFFH_WFF2  (OFFH_WFF1 + 4 * 262144)
#define WBUFH_TOT  (OFFH_WFF2 + 4 * 262144)
__device__ __half g_wbufh[WBUFH_TOT];

// CSR structures
__device__ int g_rp_nd[NNODE + 1];
__device__ int g_ci_nd[NEDGE];
__device__ int g_rp_fn[NNODE + 1];
__device__ int g_ci_fn[2 * NEDGE];
__device__ int g_rp_lg[NEDGE + 1];
__device__ int g_ci_lg[NLG];
__device__ int g_cnt[NEDGE];
__device__ int g_cur[NEDGE];
__device__ int g_bs[1024];
__device__ int g_cnt2[NNODE];
__device__ int g_cur2[NNODE];
__device__ int g_bs2[1024];

__device__ __forceinline__ float gelu_exact(float v) {
    return 0.5f * v * (1.0f + erff(v * 0.70710678118654752f));
}

__device__ __forceinline__ uint32_t pkh2(float a, float b) {
    __half2 h = __floats2half2_rn(a, b);
    return *(uint32_t*)&h;
}
__device__ __forceinline__ float2 uph2(uint32_t u) {
    __half2 h = *(__half2*)&u;
    return __half22float2(h);
}
__device__ __forceinline__ uint32_t pk2(float a, float b) { return pkh2(a, b); }

__device__ __forceinline__ void mma_f16(float* c, const uint32_t* a, const uint32_t* b) {
    asm volatile(
        "mma.sync.aligned.m16n8k16.row.col.f32.f16.f16.f32 "
        "{%0,%1,%2,%3}, {%4,%5,%6,%7}, {%8,%9}, {%0,%1,%2,%3};"
        : "+f"(c[0]), "+f"(c[1]), "+f"(c[2]), "+f"(c[3])
        : "r"(a[0]), "r"(a[1]), "r"(a[2]), "r"(a[3]), "r"(b[0]), "r"(b[1]));
}

// ---------------- CSR build kernels ----------------

__global__ void hist_kernel(const int* __restrict__ key, int* cnt, int n) {
    int i = blockIdx.x * 256 + threadIdx.x;
    if (i < n) atomicAdd(&cnt[__ldg(key + i)], 1);
}

__global__ void scan1_kernel(const int* __restrict__ in, int* __restrict__ out,
                             int* __restrict__ bsums, int n) {
    __shared__ int sh[1024];
    int i = blockIdx.x * 1024 + threadIdx.x;
    int v = (i < n) ? in[i] : 0;
    sh[threadIdx.x] = v;
    __syncthreads();
#pragma unroll
    for (int o = 1; o < 1024; o <<= 1) {
        int t = (threadIdx.x >= o) ? sh[threadIdx.x - o] : 0;
        __syncthreads();
        sh[threadIdx.x] += t;
        __syncthreads();
    }
    if (i < n) out[i] = sh[threadIdx.x] - v;
    if (threadIdx.x == 1023) bsums[blockIdx.x] = sh[1023];
}

__global__ void scan2_kernel(int* bsums, int nb) {
    __shared__ int sh[1024];
    int v = (threadIdx.x < nb) ? bsums[threadIdx.x] : 0;
    sh[threadIdx.x] = v;
    __syncthreads();
#pragma unroll
    for (int o = 1; o < 1024; o <<= 1) {
        int t = (threadIdx.x >= o) ? sh[threadIdx.x - o] : 0;
        __syncthreads();
        sh[threadIdx.x] += t;
        __syncthreads();
    }
    if (threadIdx.x < nb) bsums[threadIdx.x] = sh[threadIdx.x] - v;
}

__global__ void scan3_kernel(int* __restrict__ out, const int* __restrict__ bsums,
                             const int* __restrict__ cnt, int n) {
    int i = blockIdx.x * 1024 + threadIdx.x;
    if (i < n) {
        int v = out[i] + bsums[i >> 10];
        out[i] = v;
        if (i == n - 1) out[n] = v + cnt[i];
    }
}

__global__ void fill_kernel(const int* __restrict__ key, const int* __restrict__ val,
                            int* cursor, int* __restrict__ ci, int n) {
    int i = blockIdx.x * 256 + threadIdx.x;
    if (i >= n) return;
    int pos = atomicAdd(&cursor[__ldg(key + i)], 1);
    ci[pos] = val ? __ldg(val + i) : i;
}

// ---------------- weight pack kernels (f32 -> fp16, m16n8k16 B-fragment order) --------

// H x H (gemm1): per matrix [kt(8)][s(2)][wN(4)][nf4(4)][lane(32)] uint4
__global__ void pack256_kernel(const float* __restrict__ W, __half* __restrict__ out, int nmat) {
    int gid = blockIdx.x * 256 + threadIdx.x;
    if (gid >= nmat * 8192) return;
    int m = gid >> 13, o = gid & 8191;
    int kt = o >> 10, s = (o >> 9) & 1, wN = (o >> 7) & 3, nf4 = (o >> 5) & 3, lane = o & 31;
    int t = lane & 3, g = lane >> 2;
    int k = kt * 32 + s * 16 + 2 * t;
    int n0 = wN * 64 + nf4 * 16 + g, n1 = n0 + 8;
    const float* Wm = W + (size_t)m * 65536;
    uint4 v;
    v.x = pk2(Wm[k * 256 + n0], Wm[(k + 1) * 256 + n0]);
    v.y = pk2(Wm[(k + 8) * 256 + n0], Wm[(k + 9) * 256 + n0]);
    v.z = pk2(Wm[k * 256 + n1], Wm[(k + 1) * 256 + n1]);
    v.w = pk2(Wm[(k + 8) * 256 + n1], Wm[(k + 9) * 256 + n1]);
    ((uint4*)out)[gid] = v;
}

// w_ff1 [256,1024]: per matrix [c(4)][kt(8)][s(2)][wN(8)][nf4(2)][lane] uint4
__global__ void packff1_kernel(const float* __restrict__ W, __half* __restrict__ out, int nmat) {
    int gid = blockIdx.x * 256 + threadIdx.x;
    if (gid >= nmat * 32768) return;
    int m = gid >> 15, o = gid & 32767;
    int c = o >> 13, r = o & 8191;
    int kt = r >> 10, s = (r >> 9) & 1, wN = (r >> 6) & 7, nf4 = (r >> 5) & 1, lane = r & 31;
    int t = lane & 3, g = lane >> 2;
    int k = kt * 32 + s * 16 + 2 * t;
    int n0 = c * 256 + wN * 32 + nf4 * 16 + g, n1 = n0 + 8;
    const float* Wm = W + (size_t)m * 262144;
    uint4 v;
    v.x = pk2(Wm[k * 1024 + n0], Wm[(k + 1) * 1024 + n0]);
    v.y = pk2(Wm[(k + 8) * 1024 + n0], Wm[(k + 9) * 1024 + n0]);
    v.z = pk2(Wm[k * 1024 + n1], Wm[(k + 1) * 1024 + n1]);
    v.w = pk2(Wm[(k + 8) * 1024 + n1], Wm[(k + 9) * 1024 + n1]);
    ((uint4*)out)[gid] = v;
}

// w_ff2 [1024,256]: per matrix [c(4)][kt(8)][s(2)][wN(8)][nf4(2)][lane] uint4
__global__ void packff2_kernel(const float* __restrict__ W, __half* __restrict__ out, int nmat) {
    int gid = blockIdx.x * 256 + threadIdx.x;
    if (gid >= nmat * 32768) return;
    int m = gid >> 15, o = gid & 32767;
    int c = o >> 13, r = o & 8191;
    int kt = r >> 10, s = (r >> 9) & 1, wN = (r >> 6) & 7, nf4 = (r >> 5) & 1, lane = r & 31;
    int t = lane & 3, g = lane >> 2;
    int k = c * 256 + kt * 32 + s * 16 + 2 * t;
    int n0 = wN * 32 + nf4 * 16 + g, n1 = n0 + 8;
    const float* Wm = W + (size_t)m * 262144;
    uint4 v;
    v.x = pk2(Wm[k * 256 + n0], Wm[(k + 1) * 256 + n0]);
    v.y = pk2(Wm[(k + 8) * 256 + n0], Wm[(k + 9) * 256 + n0]);
    v.z = pk2(Wm[k * 256 + n1], Wm[(k + 1) * 256 + n1]);
    v.w = pk2(Wm[(k + 8) * 256 + n1], Wm[(k + 9) * 256 + n1]);
    ((uint4*)out)[gid] = v;
}

// ---------------- small kernels (fp16 activations) ----------------

__global__ void cvth_kernel(const float* __restrict__ in, __half* __restrict__ out, int n8) {
    int i = blockIdx.x * 256 + threadIdx.x;
    if (i >= n8) return;
    const float* p = in + (size_t)i * 8;
    float4 v0 = ((const float4*)p)[0], v1 = ((const float4*)p)[1];
    uint4 o;
    o.x = pk2(v0.x, v0.y); o.y = pk2(v0.z, v0.w);
    o.z = pk2(v1.x, v1.y); o.w = pk2(v1.z, v1.w);
    ((uint4*)out)[i] = o;
}

__global__ void embed_kernel(const float* __restrict__ rel, const int* __restrict__ feat,
                             __half* __restrict__ out) {
    int gid = blockIdx.x * 256 + threadIdx.x;
    int e = gid >> 5;
    if (e >= NEDGE) return;
    int c8 = (gid & 31) * 8;
    int r = __ldg(feat + e);
    const float* p = rel + (size_t)r * H + c8;
    float4 v0 = ((const float4*)p)[0], v1 = ((const float4*)p)[1];
    uint4 o;
    o.x = pk2(v0.x, v0.y); o.y = pk2(v0.z, v0.w);
    o.z = pk2(v1.x, v1.y); o.w = pk2(v1.z, v1.w);
    *(uint4*)(out + (size_t)e * H + c8) = o;
}

__global__ void gather2_kernel(const __half* __restrict__ x, const int* __restrict__ s,
                               const int* __restrict__ d, __half* __restrict__ out, int n) {
    int gid = blockIdx.x * 256 + threadIdx.x;
    int e = gid >> 5;
    if (e >= n) return;
    int c8 = (gid & 31) * 8;
    int si = __ldg(s + e), di = __ldg(d + e);
    uint4 ua = *(const uint4*)(x + (size_t)si * H + c8);
    uint4 ub = *(const uint4*)(x + (size_t)di * H + c8);
    const uint32_t* ap = (const uint32_t*)&ua;
    const uint32_t* bp = (const uint32_t*)&ub;
    uint4 o; uint32_t* op = (uint32_t*)&o;
#pragma unroll
    for (int i = 0; i < 4; i++) {
        float2 fa = uph2(ap[i]), fb = uph2(bp[i]);
        op[i] = pkh2(fa.x + fb.x, fa.y + fb.y);
    }
    *(uint4*)(out + (size_t)e * H + c8) = o;
}

// CSR gather segment-sum, fp16 in/out, f32 accumulate, 4-way unrolled
__global__ void segsum_kernel(const __half* __restrict__ rows, const int* __restrict__ rp,
                              const int* __restrict__ ci, __half* __restrict__ out, int nseg) {
    int row = blockIdx.x * 8 + (threadIdx.x >> 5);
    if (row >= nseg) return;
    int lane = threadIdx.x & 31;
    int beg = __ldg(rp + row), end = __ldg(rp + row + 1);
    float a[8] = {0.f,0.f,0.f,0.f,0.f,0.f,0.f,0.f};
    float b[8] = {0.f,0.f,0.f,0.f,0.f,0.f,0.f,0.f};
    int j = beg;
    for (; j + 3 < end; j += 4) {
        uint4 u0 = *(const uint4*)(rows + (size_t)__ldg(ci + j)     * H + lane * 8);
        uint4 u1 = *(const uint4*)(rows + (size_t)__ldg(ci + j + 1) * H + lane * 8);
        uint4 u2 = *(const uint4*)(rows + (size_t)__ldg(ci + j + 2) * H + lane * 8);
        uint4 u3 = *(const uint4*)(rows + (size_t)__ldg(ci + j + 3) * H + lane * 8);
        const uint32_t* p0 = (const uint32_t*)&u0;
        const uint32_t* p1 = (const uint32_t*)&u1;
        const uint32_t* p2 = (const uint32_t*)&u2;
        const uint32_t* p3 = (const uint32_t*)&u3;
#pragma unroll
        for (int i = 0; i < 4; i++) {
            float2 f0 = uph2(p0[i]); a[2*i] += f0.x; a[2*i+1] += f0.y;
            float2 f1 = uph2(p1[i]); b[2*i] += f1.x; b[2*i+1] += f1.y;
            float2 f2 = uph2(p2[i]); a[2*i] += f2.x; a[2*i+1] += f2.y;
            float2 f3 = uph2(p3[i]); b[2*i] += f3.x; b[2*i+1] += f3.y;
        }
    }
    for (; j < end; j++) {
        uint4 u = *(const uint4*)(rows + (size_t)__ldg(ci + j) * H + lane * 8);
        const uint32_t* up = (const uint32_t*)&u;
#pragma unroll
        for (int i = 0; i < 4; i++) {
            float2 f = uph2(up[i]); a[2*i] += f.x; a[2*i+1] += f.y;
        }
    }
    uint4 o; uint32_t* op = (uint32_t*)&o;
#pragma unroll
    for (int i = 0; i < 4; i++) op[i] = pkh2(a[2*i] + b[2*i], a[2*i+1] + b[2*i+1]);
    *(uint4*)(out + (size_t)row * H + lane * 8) = o;
}

__global__ void segsum_rel_kernel(const float* __restrict__ rel, const int* __restrict__ feat,
                                  const int* __restrict__ rp, const int* __restrict__ ci,
                                  __half* __restrict__ out, int nseg) {
    int row = blockIdx.x * 8 + (threadIdx.x >> 5);
    if (row >= nseg) return;
    int lane = threadIdx.x & 31;
    int beg = __ldg(rp + row), end = __ldg(rp + row + 1);
    float a[8] = {0.f,0.f,0.f,0.f,0.f,0.f,0.f,0.f};
    for (int j = beg; j < end; j++) {
        int r = __ldg(feat + __ldg(ci + j));
        const float* p = rel + (size_t)r * H + lane * 8;
        float4 v0 = ((const float4*)p)[0], v1 = ((const float4*)p)[1];
        float2 q;
        q = uph2(pk2(v0.x, v0.y)); a[0] += q.x; a[1] += q.y;
        q = uph2(pk2(v0.z, v0.w)); a[2] += q.x; a[3] += q.y;
        q = uph2(pk2(v1.x, v1.y)); a[4] += q.x; a[5] += q.y;
        q = uph2(pk2(v1.z, v1.w)); a[6] += q.x; a[7] += q.y;
    }
    uint4 o; uint32_t* op = (uint32_t*)&o;
#pragma unroll
    for (int i = 0; i < 4; i++) op[i] = pkh2(a[2*i], a[2*i+1]);
    *(uint4*)(out + (size_t)row * H + lane * 8) = o;
}

// ================= GEMM1 + LN1 fused (fp16), BM=64, m32n64 warp tile, occ 2 ==========
#define G1_SMEM_BYTES (10240 + 32768 + 5 * 1024)

struct G1Args {
    const __half* A[6];
    const __half* W[6];
    const float* Bias[6];
    const __half* xres;
    const float* gamma;
    const float* beta;
};

__global__ void __launch_bounds__(256, 2)
gemm1_ln_kernel(G1Args args, int M, __half* __restrict__ out) {
    extern __shared__ char smraw[];
    __half* As = (__half*)smraw;                // 2 x 2560 halves (stride 40)
    __half* Bs = As + 2 * 2560;                 // 2 x 8192 halves
    float* bias_s = (float*)(Bs + 2 * 8192);
    float* gs  = bias_s + 256;
    float* bt  = gs + 256;
    float* lnS = bt + 256;
    float* lnQ = lnS + 256;
    __half* xs = (__half*)smraw;                // alias after mainloop, stride 264

    int tid = threadIdx.x;
    int bm = blockIdx.x * 64;
    {
        float b = 0.f;
#pragma unroll
        for (int j = 0; j < 6; j++) b += __ldg(args.Bias[j] + tid);
        bias_s[tid] = b;
        gs[tid] = __ldg(args.gamma + tid);
        bt[tid] = __ldg(args.beta + tid);
    }

    uint32_t sbase = (uint32_t)__cvta_generic_to_shared(smraw);
    uint32_t a_base = sbase;
    uint32_t b_base = sbase + 10240;

    int warp = tid >> 5, lane = tid & 31, g = lane >> 2, t = lane & 3;
    int wm = (warp >> 2) * 32;
    int wN = warp & 3;
    int wn = wN * 64;

    float acc[2][8][4];
#pragma unroll
    for (int mt = 0; mt < 2; mt++)
#pragma unroll
        for (int nf = 0; nf < 8; nf++)
#pragma unroll
            for (int i = 0; i < 4; i++) acc[mt][nf][i] = 0.f;

    auto issue = [&](int tt, int buf) {
        int j = tt >> 3, kt = tt & 7;
        const __half* A = args.A[j];
        const uint4* Wp = (const uint4*)args.W[j] + (size_t)kt * 1024;
        {
            int r = tid >> 2, cp = tid & 3;
            int row = bm + r;
            uint32_t dst = a_base + (uint32_t)(buf * 5120 + r * 80 + cp * 16);
            const __half* src = A + (size_t)row * H + kt * 32 + cp * 8;
            int sz = (row < M) ? 16 : 0;
            asm volatile("cp.async.cg.shared.global [%0], [%1], 16, %2;\n"
                         :: "r"(dst), "l"(src), "r"(sz));
        }
#pragma unroll
        for (int i = 0; i < 4; i++) {
            int idx = tid + i * 256;
            uint32_t dst = b_base + (uint32_t)(buf * 16384 + idx * 16);
            asm volatile("cp.async.cg.shared.global [%0], [%1], 16;\n"
                         :: "r"(dst), "l"(Wp + idx));
        }
        asm volatile("cp.async.commit_group;\n");
    };

    issue(0, 0);
    for (int tt = 0; tt < 48; tt++) {
        asm volatile("cp.async.wait_group 0;\n");
        __syncthreads();
        if (tt + 1 < 48) issue(tt + 1, (tt + 1) & 1);
        const __half* Ab = As + (tt & 1) * 2560;
        const uint4* Bb4 = (const uint4*)(Bs + (tt & 1) * 8192) + wN * 128 + lane;
#pragma unroll
        for (int s = 0; s < 2; s++) {
            int k0 = s * 16 + 2 * t;
            const __half* Ar0 = Ab + (wm + g) * 40 + k0;
            const __half* Ar1 = Ab + (wm + 8 + g) * 40 + k0;
            const __half* Ar2 = Ab + (wm + 16 + g) * 40 + k0;
            const __half* Ar3 = Ab + (wm + 24 + g) * 40 + k0;
            uint32_t a0[4], a1[4];
            a0[0] = *(const uint32_t*)Ar0;
            a0[1] = *(const uint32_t*)Ar1;
            a0[2] = *(const uint32_t*)(Ar0 + 8);
            a0[3] = *(const uint32_t*)(Ar1 + 8);
            a1[0] = *(const uint32_t*)Ar2;
            a1[1] = *(const uint32_t*)Ar3;
            a1[2] = *(const uint32_t*)(Ar2 + 8);
            a1[3] = *(const uint32_t*)(Ar3 + 8);
#pragma unroll
            for (int nf4 = 0; nf4 < 4; nf4++) {
                uint4 bv = Bb4[s * 512 + nf4 * 32];
                uint32_t b0[2] = {bv.x, bv.y};
                uint32_t b1[2] = {bv.z, bv.w};
                mma_f16(acc[0][2 * nf4], a0, b0);
                mma_f16(acc[1][2 * nf4], a1, b0);
                mma_f16(acc[0][2 * nf4 + 1], a0, b1);
                mma_f16(acc[1][2 * nf4 + 1], a1, b1);
            }
        }
    }
    __syncthreads();

    // residual tile into xs (half, stride 264)
#pragma unroll
    for (int i = 0; i < 8; i++) {
        int idx = tid + i * 256;
        int r = idx >> 5, c8 = (idx & 31) * 8;
        int row = bm + r;
        uint4 v = make_uint4(0, 0, 0, 0);
        if (row < M) v = *(const uint4*)(args.xres + (size_t)row * H + c8);
        *(uint4*)(xs + r * 264 + c8) = v;
    }
    __syncthreads();

#pragma unroll
    for (int mt = 0; mt < 2; mt++) {
#pragma unroll
        for (int h = 0; h < 2; h++) {
            int row = wm + mt * 16 + h * 8 + g;
            float s = 0.f, q = 0.f;
#pragma unroll
            for (int nf = 0; nf < 8; nf++) {
                int col = wn + nf * 8 + 2 * t;
                float2 xv = uph2(*(const uint32_t*)(xs + row * 264 + col));
                float v0 = xv.x + gelu_exact(acc[mt][nf][2 * h]     + bias_s[col]);
                float v1 = xv.y + gelu_exact(acc[mt][nf][2 * h + 1] + bias_s[col + 1]);
                acc[mt][nf][2 * h] = v0; acc[mt][nf][2 * h + 1] = v1;
                s += v0 + v1; q += v0 * v0 + v1 * v1;
            }
#pragma unroll
            for (int o = 1; o <= 2; o <<= 1) {
                s += __shfl_xor_sync(0xffffffffu, s, o);
                q += __shfl_xor_sync(0xffffffffu, q, o);
            }
            if (t == 0) { lnS[row * 4 + wN] = s; lnQ[row * 4 + wN] = q; }
        }
    }
    __syncthreads();
#pragma unroll
    for (int mt = 0; mt < 2; mt++) {
#pragma unroll
        for (int h = 0; h < 2; h++) {
            int row = wm + mt * 16 + h * 8 + g;
            float S = lnS[row * 4] + lnS[row * 4 + 1] + lnS[row * 4 + 2] + lnS[row * 4 + 3];
            float Q = lnQ[row * 4] + lnQ[row * 4 + 1] + lnQ[row * 4 + 2] + lnQ[row * 4 + 3];
            float m = S * (1.f / H), v = Q * (1.f / H) - m * m, rs = rsqrtf(v + 1e-5f);
            if (bm + row < M) {
#pragma unroll
                for (int nf = 0; nf < 8; nf++) {
                    int col = wn + nf * 8 + 2 * t;
                    float o0 = (acc[mt][nf][2 * h]     - m) * rs * gs[col]     + bt[col];
                    float o1 = (acc[mt][nf][2 * h + 1] - m) * rs * gs[col + 1] + bt[col + 1];
                    *(uint32_t*)(out + (size_t)(bm + row) * H + col) = pkh2(o0, o1);
                }
            }
        }
    }
}

// ================= fused FFN + LN2 (fp16), 4 chunks of 256, mW=2 x nW=8 =============
#define F_SMEM_BYTES (33792 + 33792 + 32768 + 8192)   // 108544

struct FArgs {
    const __half* w1;
    const float* b1;
    const __half* w2;
    const float* b2;
    const float* gamma;
    const float* beta;
};

__global__ void __launch_bounds__(512, 1)
ffn_kernel(FArgs args, int M, const __half* __restrict__ in1,
           void* __restrict__ outv, int out_half) {
    extern __shared__ char smraw[];
    __half* xs  = (__half*)smraw;            // 64 x 264 halves
    __half* hb  = xs + 64 * 264;             // 64 x 264 halves (256 used)
    __half* Bst = hb + 64 * 264;             // 2 x 8192 halves
    float* b2s = (float*)(Bst + 2 * 8192);
    float* gs  = b2s + 256;
    float* bt  = gs + 256;
    float* b1c = bt + 256;
    float* lnS = b1c + 256;
    float* lnQ = lnS + 512;

    int tid = threadIdx.x;
    int bm = blockIdx.x * 64;

    if (tid < 256) {
        b2s[tid] = __ldg(args.b2 + tid);
        gs[tid]  = __ldg(args.gamma + tid);
        bt[tid]  = __ldg(args.beta + tid);
    }
#pragma unroll
    for (int i = 0; i < 4; i++) {
        int idx = tid + i * 512;
        int r = idx >> 5, c8 = (idx & 31) * 8;
        int row = bm + r;
        uint4 v = make_uint4(0, 0, 0, 0);
        if (row < M) v = *(const uint4*)(in1 + (size_t)row * H + c8);
        *(uint4*)(xs + r * 264 + c8) = v;
    }

    uint32_t bst_base = (uint32_t)__cvta_generic_to_shared(Bst);
    int warp = tid >> 5, lane = tid & 31, g = lane >> 2, t = lane & 3;
    int wm = (warp >> 3) * 32;
    int wN = warp & 7;
    int wn = wN * 32;

    float acc2[2][4][4];
#pragma unroll
    for (int mt = 0; mt < 2; mt++)
#pragma unroll
        for (int nf = 0; nf < 4; nf++)
#pragma unroll
            for (int i = 0; i < 4; i++) acc2[mt][nf][i] = 0.f;

    __syncthreads();

    for (int c = 0; c < 4; c++) {
        if (c > 0) __syncthreads();
        if (tid < 256) b1c[tid] = __ldg(args.b1 + c * 256 + tid);

        float acc1[2][4][4];
#pragma unroll
        for (int mt = 0; mt < 2; mt++)
#pragma unroll
            for (int nf = 0; nf < 4; nf++)
#pragma unroll
                for (int i = 0; i < 4; i++) acc1[mt][nf][i] = 0.f;

        const uint4* W1p = (const uint4*)args.w1 + (size_t)c * 8192;
        auto issue1 = [&](int kt, int buf) {
#pragma unroll
            for (int i = 0; i < 2; i++) {
                int idx = tid + i * 512;
                uint32_t dst = bst_base + (uint32_t)(buf * 16384 + idx * 16);
                asm volatile("cp.async.cg.shared.global [%0], [%1], 16;\n"
                             :: "r"(dst), "l"(W1p + kt * 1024 + idx));
            }
            asm volatile("cp.async.commit_group;\n");
        };

        issue1(0, 0);
        for (int kt = 0; kt < 8; kt++) {
            asm volatile("cp.async.wait_group 0;\n");
            __syncthreads();
            if (kt + 1 < 8) issue1(kt + 1, (kt + 1) & 1);
            const uint4* Bb4 = (const uint4*)(Bst + (kt & 1) * 8192) + wN * 64 + lane;
#pragma unroll
            for (int s = 0; s < 2; s++) {
                int kg = kt * 32 + s * 16 + 2 * t;
                const __half* Ar0 = xs + (wm + g) * 264 + kg;
                const __half* Ar1 = xs + (wm + 8 + g) * 264 + kg;
                const __half* Ar2 = xs + (wm + 16 + g) * 264 + kg;
                const __half* Ar3 = xs + (wm + 24 + g) * 264 + kg;
                uint32_t a0[4], a1[4];
                a0[0] = *(const uint32_t*)Ar0;
                a0[1] = *(const uint32_t*)Ar1;
                a0[2] = *(const uint32_t*)(Ar0 + 8);
                a0[3] = *(const uint32_t*)(Ar1 + 8);
                a1[0] = *(const uint32_t*)Ar2;
                a1[1] = *(const uint32_t*)Ar3;
                a1[2] = *(const uint32_t*)(Ar2 + 8);
                a1[3] = *(const uint32_t*)(Ar3 + 8);
#pragma unroll
                for (int nf4 = 0; nf4 < 2; nf4++) {
                    uint4 bv = Bb4[s * 512 + nf4 * 32];
                    uint32_t b0[2] = {bv.x, bv.y};
                    uint32_t b1[2] = {bv.z, bv.w};
                    mma_f16(acc1[0][2 * nf4], a0, b0);
                    mma_f16(acc1[1][2 * nf4], a1, b0);
                    mma_f16(acc1[0][2 * nf4 + 1], a0, b1);
                    mma_f16(acc1[1][2 * nf4 + 1], a1, b1);
                }
            }
        }

#pragma unroll
        for (int mt = 0; mt < 2; mt++) {
#pragma unroll
            for (int nf = 0; nf < 4; nf++) {
                int col = wn + nf * 8 + 2 * t;
                float h0 = gelu_exact(acc1[mt][nf][0] + b1c[col]);
                float h1 = gelu_exact(acc1[mt][nf][1] + b1c[col + 1]);
                float h2v = gelu_exact(acc1[mt][nf][2] + b1c[col]);
                float h3v = gelu_exact(acc1[mt][nf][3] + b1c[col + 1]);
                *(uint32_t*)(hb + (wm + mt * 16 + g) * 264 + col)     = pkh2(h0, h1);
                *(uint32_t*)(hb + (wm + mt * 16 + 8 + g) * 264 + col) = pkh2(h2v, h3v);
            }
        }
        __syncthreads();

        const uint4* W2p = (const uint4*)args.w2 + (size_t)c * 8192;
        auto issue2 = [&](int kt, int buf) {
#pragma unroll
            for (int i = 0; i < 2; i++) {
                int idx = tid + i * 512;
                uint32_t dst = bst_base + (uint32_t)(buf * 16384 + idx * 16);
                asm volatile("cp.async.cg.shared.global [%0], [%1], 16;\n"
                             :: "r"(dst), "l"(W2p + kt * 1024 + idx));
            }
            asm volatile("cp.async.commit_group;\n");
        };

        issue2(0, 0);
        for (int kt = 0; kt < 8; kt++) {
            asm volatile("cp.async.wait_group 0;\n");
            __syncthreads();
            if (kt + 1 < 8) issue2(kt + 1, (kt + 1) & 1);
            const uint4* Bb4 = (const uint4*)(Bst + (kt & 1) * 8192) + wN * 64 + lane;
#pragma unroll
            for (int s = 0; s < 2; s++) {
                int kg = kt * 32 + s * 16 + 2 * t;
                const __half* Ar0 = hb + (wm + g) * 264 + kg;
                const __half* Ar1 = hb + (wm + 8 + g) * 264 + kg;
                const __half* Ar2 = hb + (wm + 16 + g) * 264 + kg;
                const __half* Ar3 = hb + (wm + 24 + g) * 264 + kg;
                uint32_t a0[4], a1[4];
                a0[0] = *(const uint32_t*)Ar0;
                a0[1] = *(const uint32_t*)Ar1;
                a0[2] = *(const uint32_t*)(Ar0 + 8);
                a0[3] = *(const uint32_t*)(Ar1 + 8);
                a1[0] = *(const uint32_t*)Ar2;
                a1[1] = *(const uint32_t*)Ar3;
                a1[2] = *(const uint32_t*)(Ar2 + 8);
                a1[3] = *(const uint32_t*)(Ar3 + 8);
#pragma unroll
                for (int nf4 = 0; nf4 < 2; nf4++) {
                    uint4 bv = Bb4[s * 512 + nf4 * 32];
                    uint32_t b0[2] = {bv.x, bv.y};
                    uint32_t b1[2] = {bv.z, bv.w};
                    mma_f16(acc2[0][2 * nf4], a0, b0);
                    mma_f16(acc2[1][2 * nf4], a1, b0);
                    mma_f16(acc2[0][2 * nf4 + 1], a0, b1);
                    mma_f16(acc2[1][2 * nf4 + 1], a1, b1);
                }
            }
        }
    }

    // LN2 epilogue
#pragma unroll
    for (int mt = 0; mt < 2; mt++) {
#pragma unroll
        for (int h = 0; h < 2; h++) {
            int row = wm + mt * 16 + h * 8 + g;
            float s = 0.f, q = 0.f;
#pragma unroll
            for (int nf = 0; nf < 4; nf++) {
                int col = wn + nf * 8 + 2 * t;
                float2 xv = uph2(*(const uint32_t*)(xs + row * 264 + col));
                float v0 = xv.x + acc2[mt][nf][2 * h]     + b2s[col];
                float v1 = xv.y + acc2[mt][nf][2 * h + 1] + b2s[col + 1];
                acc2[mt][nf][2 * h] = v0; acc2[mt][nf][2 * h + 1] = v1;
                s += v0 + v1; q += v0 * v0 + v1 * v1;
            }
#pragma unroll
            for (int o = 1; o <= 2; o <<= 1) {
                s += __shfl_xor_sync(0xffffffffu, s, o);
                q += __shfl_xor_sync(0xffffffffu, q, o);
            }
            if (t == 0) { lnS[row * 8 + wN] = s; lnQ[row * 8 + wN] = q; }
        }
    }
    __syncthreads();
#pragma unroll
    for (int mt = 0; mt < 2; mt++) {
#pragma unroll
        for (int h = 0; h < 2; h++) {
            int row = wm + mt * 16 + h * 8 + g;
            float S = 0.f, Q = 0.f;
#pragma unroll
            for (int i = 0; i < 8; i++) { S += lnS[row * 8 + i]; Q += lnQ[row * 8 + i]; }
            float m = S * (1.f / H), v = Q * (1.f / H) - m * m, rs = rsqrtf(v + 1e-5f);
            if (bm + row < M) {
#pragma unroll
                for (int nf = 0; nf < 4; nf++) {
                    int col = wn + nf * 8 + 2 * t;
                    float o0 = (acc2[mt][nf][2 * h]     - m) * rs * gs[col]     + bt[col];
                    float o1 = (acc2[mt][nf][2 * h + 1] - m) * rs * gs[col + 1] + bt[col + 1];
                    if (out_half) {
                        *(uint32_t*)((__half*)outv + (size_t)(bm + row) * H + col) = pkh2(o0, o1);
                    } else {
                        *(float2*)((float*)outv + (size_t)(bm + row) * H + col) = make_float2(o0, o1);
                    }
                }
            }
        }
    }
}

// ---------------- host orchestration ----------------

struct Net {
    const float *b_self, *b_khop, *b_fuse, *b_ff1, *b_ff2;
    const float *ln1g, *ln1b, *ln2g, *ln2b;
    __half* wbuf;
};

static void run_core(const Net& n, int l, int c, int M, __half* const* z,
                     const __half* xin, const __half* fused, __half* out1buf,
                     void* outp, int out_half, cudaStream_t st) {
    size_t lc = (size_t)(l * 2 + c);
    G1Args ga;
    ga.A[0] = xin;
    ga.W[0] = n.wbuf + OFFH_WSELF + lc * 65536;
    ga.Bias[0] = n.b_self + lc * H;
    for (int i = 0; i < 4; i++) {
        ga.A[1 + i] = z[i];
        ga.W[1 + i] = n.wbuf + OFFH_WKHOP + (lc * 4 + i) * (size_t)65536;
        ga.Bias[1 + i] = n.b_khop + (lc * 4 + i) * (size_t)H;
    }
    ga.A[5] = fused;
    ga.W[5] = n.wbuf + OFFH_WFUSE + lc * 65536;
    ga.Bias[5] = n.b_fuse + lc * H;
    ga.xres = xin;
    ga.gamma = n.ln1g + lc * H;
    ga.beta  = n.ln1b + lc * H;

    gemm1_ln_kernel<<<(M + 63) / 64, 256, G1_SMEM_BYTES, st>>>(ga, M, out1buf);

    FArgs fa;
    fa.w1 = n.wbuf + OFFH_WFF1 + lc * (size_t)262144;
    fa.b1 = n.b_ff1 + lc * FH;
    fa.w2 = n.wbuf + OFFH_WFF2 + lc * (size_t)262144;
    fa.b2 = n.b_ff2 + lc * H;
    fa.gamma = n.ln2g + lc * H;
    fa.beta  = n.ln2b + lc * H;
    ffn_kernel<<<(M + 63) / 64, 512, F_SMEM_BYTES, st>>>(fa, M, out1buf, outp, out_half);
}

static void exclusive_scan(int* cnt, int* rp, int* bsums, int n, cudaStream_t st) {
    int nb = (n + 1023) / 1024;
    scan1_kernel<<<nb, 1024, 0, st>>>(cnt, rp, bsums, n);
    scan2_kernel<<<1, 1024, 0, st>>>(bsums, nb);
    scan3_kernel<<<nb, 1024, 0, st>>>(rp, bsums, cnt, n);
}

extern "C" void kernel_launch(void* const* d_in, const int* in_sizes, int n_in,
                              void* d_out, int out_size) {
    const float* x_in = (const float*)d_in[0];
    const int* feat   = (const int*)d_in[1];
    const int* eig    = (const int*)d_in[2];
    const int* eil    = (const int*)d_in[3];
    const float* rel  = (const float*)d_in[4];

    const float* w_self = (const float*)d_in[5];
    const float* w_khop = (const float*)d_in[7];
    const float* w_fuse = (const float*)d_in[9];
    const float* w_ff1  = (const float*)d_in[11];
    const float* w_ff2  = (const float*)d_in[13];

    Net n;
    n.b_self = (const float*)d_in[6];
    n.b_khop = (const float*)d_in[8];
    n.b_fuse = (const float*)d_in[10];
    n.b_ff1  = (const float*)d_in[12];
    n.b_ff2  = (const float*)d_in[14];
    n.ln1g   = (const float*)d_in[15]; n.ln1b = (const float*)d_in[16];
    n.ln2g   = (const float*)d_in[17]; n.ln2b = (const float*)d_in[18];

    cudaFuncSetAttribute(gemm1_ln_kernel,
                         cudaFuncAttributeMaxDynamicSharedMemorySize, G1_SMEM_BYTES);
    cudaFuncSetAttribute(ffn_kernel,
                         cudaFuncAttributeMaxDynamicSharedMemorySize, F_SMEM_BYTES);

    static cudaStream_t s2 = nullptr;
    static cudaEvent_t ev_start, ev_prep, ev_x0, ev_lg0, ev_fin;
    if (!s2) {
        cudaStreamCreateWithFlags(&s2, cudaStreamNonBlocking);
        cudaEventCreateWithFlags(&ev_start, cudaEventDisableTiming);
        cudaEventCreateWithFlags(&ev_prep,  cudaEventDisableTiming);
        cudaEventCreateWithFlags(&ev_x0,    cudaEventDisableTiming);
        cudaEventCreateWithFlags(&ev_lg0,   cudaEventDisableTiming);
        cudaEventCreateWithFlags(&ev_fin,   cudaEventDisableTiming);
    }

    __half *px0, *plg0, *pfn, *pfe, *pfe2, *pzbase, *pznb, *pout1, *pout1n, *pwbuf;
    int *rp_nd, *ci_nd, *rp_fn, *ci_fn, *rp_lg, *ci_lg;
    int *pcnt, *pcur, *pbs, *pcnt2, *pcur2, *pbs2;
    cudaGetSymbolAddress((void**)&px0,   h_x);
    cudaGetSymbolAddress((void**)&plg0,  h_lg);
    cudaGetSymbolAddress((void**)&pfn,   h_fn);
    cudaGetSymbolAddress((void**)&pfe,   h_fe);
    cudaGetSymbolAddress((void**)&pfe2,  h_fe2);
    cudaGetSymbolAddress((void**)&pzbase,h_z);
    cudaGetSymbolAddress((void**)&pznb,  h_zn);
    cudaGetSymbolAddress((void**)&pout1, h_out1);
    cudaGetSymbolAddress((void**)&pout1n,h_out1n);
    cudaGetSymbolAddress((void**)&pwbuf, g_wbufh);
    cudaGetSymbolAddress((void**)&rp_nd, g_rp_nd);
    cudaGetSymbolAddress((void**)&ci_nd, g_ci_nd);
    cudaGetSymbolAddress((void**)&rp_fn, g_rp_fn);
    cudaGetSymbolAddress((void**)&ci_fn, g_ci_fn);
    cudaGetSymbolAddress((void**)&rp_lg, g_rp_lg);
    cudaGetSymbolAddress((void**)&ci_lg, g_ci_lg);
    cudaGetSymbolAddress((void**)&pcnt,  g_cnt);
    cudaGetSymbolAddress((void**)&pcur,  g_cur);
    cudaGetSymbolAddress((void**)&pbs,   g_bs);
    cudaGetSymbolAddress((void**)&pcnt2, g_cnt2);
    cudaGetSymbolAddress((void**)&pcur2, g_cur2);
    cudaGetSymbolAddress((void**)&pbs2,  g_bs2);

    n.wbuf = pwbuf;
    __half* px[2]  = {px0,  px0  + (size_t)NNODE * H};
    __half* plg[2] = {plg0, plg0 + (size_t)NEDGE * H};
    __half* ze[4]; __half* zn[4];
    for (int i = 0; i < 4; i++) {
        ze[i] = pzbase + (size_t)i * NEDGE * H;
        zn[i] = pznb + (size_t)i * NNODE * H;
    }

    const int* src_g = eig;  const int* dst_g = eig + NEDGE;
    const int* src_l = eil;  const int* dst_l = eil + NLG;

    // fork point for capture
    cudaEventRecord(ev_start, 0);
    cudaStreamWaitEvent(s2, ev_start, 0);

    // ===== stream 0: lg CSR + layer-0 edge khops =====
    cudaMemsetAsync(pcnt, 0, NEDGE * sizeof(int), 0);
    hist_kernel<<<(NLG + 255) / 256, 256>>>(dst_l, pcnt, NLG);
    exclusive_scan(pcnt, rp_lg, pbs, NEDGE, 0);
    cudaMemcpyAsync(pcur, rp_lg, NEDGE * sizeof(int), cudaMemcpyDeviceToDevice, 0);
    fill_kernel<<<(NLG + 255) / 256, 256>>>(dst_l, src_l, pcur, ci_lg, NLG);

    segsum_rel_kernel<<<(NEDGE + 7) / 8, 256>>>(rel, feat, rp_lg, ci_lg, ze[0], NEDGE);
    segsum_kernel<<<(NEDGE + 7) / 8, 256>>>(ze[0], rp_lg, ci_lg, ze[1], NEDGE);
    segsum_kernel<<<(NEDGE + 7) / 8, 256>>>(ze[1], rp_lg, ci_lg, ze[2], NEDGE);
    segsum_kernel<<<(NEDGE + 7) / 8, 256>>>(ze[2], rp_lg, ci_lg, ze[3], NEDGE);

    // ===== stream s2: packs + init + gather2-l0 =====
    cvth_kernel<<<(NNODE * H / 8 + 255) / 256, 256, 0, s2>>>(x_in, px[0], NNODE * H / 8);
    embed_kernel<<<NEDGE * 32 / 256, 256, 0, s2>>>(rel, feat, plg[0]);
    pack256_kernel<<<(4 * 8192 + 255) / 256, 256, 0, s2>>>(w_self, pwbuf + OFFH_WSELF, 4);
    pack256_kernel<<<(16 * 8192 + 255) / 256, 256, 0, s2>>>(w_khop, pwbuf + OFFH_WKHOP, 16);
    pack256_kernel<<<(4 * 8192 + 255) / 256, 256, 0, s2>>>(w_fuse, pwbuf + OFFH_WFUSE, 4);
    packff1_kernel<<<(4 * 32768 + 255) / 256, 256, 0, s2>>>(w_ff1, pwbuf + OFFH_WFF1, 4);
    packff2_kernel<<<(4 * 32768 + 255) / 256, 256, 0, s2>>>(w_ff2, pwbuf + OFFH_WFF2, 4);
    gather2_kernel<<<NEDGE * 32 / 256, 256, 0, s2>>>(px[0], src_g, dst_g, pfe, NEDGE);
    cudaEventRecord(ev_prep, s2);

    // ===== stream s2: node CSRs + node core layer 0 =====
    cudaMemsetAsync(pcnt2, 0, NNODE * sizeof(int), s2);
    hist_kernel<<<(NEDGE + 255) / 256, 256, 0, s2>>>(dst_g, pcnt2, NEDGE);
    exclusive_scan(pcnt2, rp_nd, pbs2, NNODE, s2);
    cudaMemcpyAsync(pcur2, rp_nd, NNODE * sizeof(int), cudaMemcpyDeviceToDevice, s2);
    fill_kernel<<<(NEDGE + 255) / 256, 256, 0, s2>>>(dst_g, src_g, pcur2, ci_nd, NEDGE);

    cudaMemsetAsync(pcnt2, 0, NNODE * sizeof(int), s2);
    hist_kernel<<<(NEDGE + 255) / 256, 256, 0, s2>>>(src_g, pcnt2, NEDGE);
    hist_kernel<<<(NEDGE + 255) / 256, 256, 0, s2>>>(dst_g, pcnt2, NEDGE);
    exclusive_scan(pcnt2, rp_fn, pbs2, NNODE, s2);
    cudaMemcpyAsync(pcur2, rp_fn, NNODE * sizeof(int), cudaMemcpyDeviceToDevice, s2);
    fill_kernel<<<(NEDGE + 255) / 256, 256, 0, s2>>>(src_g, nullptr, pcur2, ci_fn, NEDGE);
    fill_kernel<<<(NEDGE + 255) / 256, 256, 0, s2>>>(dst_g, nullptr, pcur2, ci_fn, NEDGE);

    segsum_kernel<<<(NNODE + 7) / 8, 256, 0, s2>>>(plg[0], rp_fn, ci_fn, pfn, NNODE);
    {
        const __half* prev = px[0];
        for (int i = 0; i < 4; i++) {
            segsum_kernel<<<(NNODE + 7) / 8, 256, 0, s2>>>(prev, rp_nd, ci_nd, zn[i], NNODE);
            prev = zn[i];
        }
    }
    run_core(n, 0, 0, NNODE, zn, px[0], pfn, pout1n, px[1], 1, s2);
    gather2_kernel<<<NEDGE * 32 / 256, 256, 0, s2>>>(px[1], src_g, dst_g, pfe2, NEDGE);
    cudaEventRecord(ev_x0, s2);

    // ===== stream 0: edge core, layer 0 =====
    cudaStreamWaitEvent(0, ev_prep, 0);
    run_core(n, 0, 1, NEDGE, ze, plg[0], pfe, pout1, plg[1], 1, (cudaStream_t)0);
    cudaEventRecord(ev_lg0, 0);

    // ===== stream s2: node core, layer 1 =====
    cudaStreamWaitEvent(s2, ev_lg0, 0);
    segsum_kernel<<<(NNODE + 7) / 8, 256, 0, s2>>>(plg[1], rp_fn, ci_fn, pfn, NNODE);
    {
        const __half* prev = px[1];
        for (int i = 0; i < 4; i++) {
            segsum_kernel<<<(NNODE + 7) / 8, 256, 0, s2>>>(prev, rp_nd, ci_nd, zn[i], NNODE);
            prev = zn[i];
        }
    }
    run_core(n, 1, 0, NNODE, zn, px[1], pfn, pout1n, (float*)d_out, 0, s2);
    cudaEventRecord(ev_fin, s2);

    // ===== stream 0: edge core, layer 1 =====
    {
        const __half* prev = plg[1];
        for (int i = 0; i < 4; i++) {
            segsum_kernel<<<(NEDGE + 7) / 8, 256>>>(prev, rp_lg, ci_lg, ze[i], NEDGE);
            prev = ze[i];
        }
    }
    cudaStreamWaitEvent(0, ev_x0, 0);
    run_core(n, 1, 1, NEDGE, ze, plg[1], pfe2, pout1,
             (float*)d_out + (size_t)NNODE * H, 0, (cudaStream_t)0);

    cudaStreamWaitEvent(0, ev_fin, 0);
    (void)in_sizes; (void)n_in; (void)out_size;
}

// round 15
// speedup vs baseline: 1.0785x; 1.0259x over previous
#include <cuda_runtime.h>
#include <cuda_fp16.h>
#include <cstdint>
#include <math.h>

#define H       256
#define FH      1024
#define NNODE   20000
#define NEDGE   160000
#define NLG     640000

// ---------------- scratch (static device memory; no allocations) ----------------
__device__ __half h_x[2][(size_t)NNODE * H];
__device__ __half h_lg[2][(size_t)NEDGE * H];
__device__ __half h_fn[(size_t)NNODE * H];
__device__ __half h_fe[(size_t)NEDGE * H];
__device__ __half h_fe2[(size_t)NEDGE * H];
__device__ __half h_z[4][(size_t)NEDGE * H];
__device__ __half h_zn[4][(size_t)NNODE * H];
__device__ __half h_out1[(size_t)NEDGE * H];
__device__ __half h_out1n[(size_t)NNODE * H];

// packed fp16 weights (fragment order for mma.m16n8k16)
#define OFFH_WSELF 0
#define OFFH_WKHOP (OFFH_WSELF + 4 * 65536)
#define OFFH_WFUSE (OFFH_WKHOP + 16 * 65536)
#define OFFH_WFF1  (OFFH_WFUSE + 4 * 65536)
#define OFFH_WFF2  (OFFH_WFF1 + 4 * 262144)
#define WBUFH_TOT  (OFFH_WFF2 + 4 * 262144)
__device__ __half g_wbufh[WBUFH_TOT];

// CSR structures
__device__ int g_rp_nd[NNODE + 1];
__device__ int g_ci_nd[NEDGE];
__device__ int g_rp_fn[NNODE + 1];
__device__ int g_ci_fn[2 * NEDGE];
__device__ int g_rp_lg[NEDGE + 1];
__device__ int g_ci_lg[NLG];
__device__ int g_cnt[NEDGE];
__device__ int g_cur[NEDGE];
__device__ int g_bs[1024];
__device__ int g_cnt2[NNODE];
__device__ int g_cur2[NNODE];
__device__ int g_bs2[1024];

__device__ __forceinline__ float gelu_exact(float v) {
    return 0.5f * v * (1.0f + erff(v * 0.70710678118654752f));
}

__device__ __forceinline__ uint32_t pkh2(float a, float b) {
    __half2 h = __floats2half2_rn(a, b);
    return *(uint32_t*)&h;
}
__device__ __forceinline__ float2 uph2(uint32_t u) {
    __half2 h = *(__half2*)&u;
    return __half22float2(h);
}
__device__ __forceinline__ uint32_t pk2(float a, float b) { return pkh2(a, b); }

__device__ __forceinline__ void mma_f16(float* c, const uint32_t* a, const uint32_t* b) {
    asm volatile(
        "mma.sync.aligned.m16n8k16.row.col.f32.f16.f16.f32 "
        "{%0,%1,%2,%3}, {%4,%5,%6,%7}, {%8,%9}, {%0,%1,%2,%3};"
        : "+f"(c[0]), "+f"(c[1]), "+f"(c[2]), "+f"(c[3])
        : "r"(a[0]), "r"(a[1]), "r"(a[2]), "r"(a[3]), "r"(b[0]), "r"(b[1]));
}

// ---------------- CSR build kernels ----------------

__global__ void hist_kernel(const int* __restrict__ key, int* cnt, int n) {
    int i = blockIdx.x * 256 + threadIdx.x;
    if (i < n) atomicAdd(&cnt[__ldg(key + i)], 1);
}

__global__ void scan1_kernel(const int* __restrict__ in, int* __restrict__ out,
                             int* __restrict__ bsums, int n) {
    __shared__ int sh[1024];
    int i = blockIdx.x * 1024 + threadIdx.x;
    int v = (i < n) ? in[i] : 0;
    sh[threadIdx.x] = v;
    __syncthreads();
#pragma unroll
    for (int o = 1; o < 1024; o <<= 1) {
        int t = (threadIdx.x >= o) ? sh[threadIdx.x - o] : 0;
        __syncthreads();
        sh[threadIdx.x] += t;
        __syncthreads();
    }
    if (i < n) out[i] = sh[threadIdx.x] - v;
    if (threadIdx.x == 1023) bsums[blockIdx.x] = sh[1023];
}

__global__ void scan2_kernel(int* bsums, int nb) {
    __shared__ int sh[1024];
    int v = (threadIdx.x < nb) ? bsums[threadIdx.x] : 0;
    sh[threadIdx.x] = v;
    __syncthreads();
#pragma unroll
    for (int o = 1; o < 1024; o <<= 1) {
        int t = (threadIdx.x >= o) ? sh[threadIdx.x - o] : 0;
        __syncthreads();
        sh[threadIdx.x] += t;
        __syncthreads();
    }
    if (threadIdx.x < nb) bsums[threadIdx.x] = sh[threadIdx.x] - v;
}

__global__ void scan3_kernel(int* __restrict__ out, const int* __restrict__ bsums,
                             const int* __restrict__ cnt, int n) {
    int i = blockIdx.x * 1024 + threadIdx.x;
    if (i < n) {
        int v = out[i] + bsums[i >> 10];
        out[i] = v;
        if (i == n - 1) out[n] = v + cnt[i];
    }
}

__global__ void fill_kernel(const int* __restrict__ key, const int* __restrict__ val,
                            int* cursor, int* __restrict__ ci, int n) {
    int i = blockIdx.x * 256 + threadIdx.x;
    if (i >= n) return;
    int pos = atomicAdd(&cursor[__ldg(key + i)], 1);
    ci[pos] = val ? __ldg(val + i) : i;
}

// ---------------- weight pack kernels (f32 -> fp16, m16n8k16 B-fragment order) --------

// H x H (gemm1): per matrix [kt(8)][s(2)][wN(4)][nf4(4)][lane(32)] uint4
__global__ void pack256_kernel(const float* __restrict__ W, __half* __restrict__ out, int nmat) {
    int gid = blockIdx.x * 256 + threadIdx.x;
    if (gid >= nmat * 8192) return;
    int m = gid >> 13, o = gid & 8191;
    int kt = o >> 10, s = (o >> 9) & 1, wN = (o >> 7) & 3, nf4 = (o >> 5) & 3, lane = o & 31;
    int t = lane & 3, g = lane >> 2;
    int k = kt * 32 + s * 16 + 2 * t;
    int n0 = wN * 64 + nf4 * 16 + g, n1 = n0 + 8;
    const float* Wm = W + (size_t)m * 65536;
    uint4 v;
    v.x = pk2(Wm[k * 256 + n0], Wm[(k + 1) * 256 + n0]);
    v.y = pk2(Wm[(k + 8) * 256 + n0], Wm[(k + 9) * 256 + n0]);
    v.z = pk2(Wm[k * 256 + n1], Wm[(k + 1) * 256 + n1]);
    v.w = pk2(Wm[(k + 8) * 256 + n1], Wm[(k + 9) * 256 + n1]);
    ((uint4*)out)[gid] = v;
}

// w_ff1 [256,1024]: per matrix [c(4)][kt(8)][s(2)][wN(8)][nf4(2)][lane] uint4
__global__ void packff1_kernel(const float* __restrict__ W, __half* __restrict__ out, int nmat) {
    int gid = blockIdx.x * 256 + threadIdx.x;
    if (gid >= nmat * 32768) return;
    int m = gid >> 15, o = gid & 32767;
    int c = o >> 13, r = o & 8191;
    int kt = r >> 10, s = (r >> 9) & 1, wN = (r >> 6) & 7, nf4 = (r >> 5) & 1, lane = r & 31;
    int t = lane & 3, g = lane >> 2;
    int k = kt * 32 + s * 16 + 2 * t;
    int n0 = c * 256 + wN * 32 + nf4 * 16 + g, n1 = n0 + 8;
    const float* Wm = W + (size_t)m * 262144;
    uint4 v;
    v.x = pk2(Wm[k * 1024 + n0], Wm[(k + 1) * 1024 + n0]);
    v.y = pk2(Wm[(k + 8) * 1024 + n0], Wm[(k + 9) * 1024 + n0]);
    v.z = pk2(Wm[k * 1024 + n1], Wm[(k + 1) * 1024 + n1]);
    v.w = pk2(Wm[(k + 8) * 1024 + n1], Wm[(k + 9) * 1024 + n1]);
    ((uint4*)out)[gid] = v;
}

// w_ff2 [1024,256]: per matrix [c(4)][kt(8)][s(2)][wN(8)][nf4(2)][lane] uint4
__global__ void packff2_kernel(const float* __restrict__ W, __half* __restrict__ out, int nmat) {
    int gid = blockIdx.x * 256 + threadIdx.x;
    if (gid >= nmat * 32768) return;
    int m = gid >> 15, o = gid & 32767;
    int c = o >> 13, r = o & 8191;
    int kt = r >> 10, s = (r >> 9) & 1, wN = (r >> 6) & 7, nf4 = (r >> 5) & 1, lane = r & 31;
    int t = lane & 3, g = lane >> 2;
    int k = c * 256 + kt * 32 + s * 16 + 2 * t;
    int n0 = wN * 32 + nf4 * 16 + g, n1 = n0 + 8;
    const float* Wm = W + (size_t)m * 262144;
    uint4 v;
    v.x = pk2(Wm[k * 256 + n0], Wm[(k + 1) * 256 + n0]);
    v.y = pk2(Wm[(k + 8) * 256 + n0], Wm[(k + 9) * 256 + n0]);
    v.z = pk2(Wm[k * 256 + n1], Wm[(k + 1) * 256 + n1]);
    v.w = pk2(Wm[(k + 8) * 256 + n1], Wm[(k + 9) * 256 + n1]);
    ((uint4*)out)[gid] = v;
}

// ---------------- small kernels (fp16 activations) ----------------

__global__ void cvth_kernel(const float* __restrict__ in, __half* __restrict__ out, int n8) {
    int i = blockIdx.x * 256 + threadIdx.x;
    if (i >= n8) return;
    const float* p = in + (size_t)i * 8;
    float4 v0 = ((const float4*)p)[0], v1 = ((const float4*)p)[1];
    uint4 o;
    o.x = pk2(v0.x, v0.y); o.y = pk2(v0.z, v0.w);
    o.z = pk2(v1.x, v1.y); o.w = pk2(v1.z, v1.w);
    ((uint4*)out)[i] = o;
}

__global__ void embed_kernel(const float* __restrict__ rel, const int* __restrict__ feat,
                             __half* __restrict__ out) {
    int gid = blockIdx.x * 256 + threadIdx.x;
    int e = gid >> 5;
    if (e >= NEDGE) return;
    int c8 = (gid & 31) * 8;
    int r = __ldg(feat + e);
    const float* p = rel + (size_t)r * H + c8;
    float4 v0 = ((const float4*)p)[0], v1 = ((const float4*)p)[1];
    uint4 o;
    o.x = pk2(v0.x, v0.y); o.y = pk2(v0.z, v0.w);
    o.z = pk2(v1.x, v1.y); o.w = pk2(v1.z, v1.w);
    *(uint4*)(out + (size_t)e * H + c8) = o;
}

__global__ void gather2_kernel(const __half* __restrict__ x, const int* __restrict__ s,
                               const int* __restrict__ d, __half* __restrict__ out, int n) {
    int gid = blockIdx.x * 256 + threadIdx.x;
    int e = gid >> 5;
    if (e >= n) return;
    int c8 = (gid & 31) * 8;
    int si = __ldg(s + e), di = __ldg(d + e);
    uint4 ua = *(const uint4*)(x + (size_t)si * H + c8);
    uint4 ub = *(const uint4*)(x + (size_t)di * H + c8);
    const uint32_t* ap = (const uint32_t*)&ua;
    const uint32_t* bp = (const uint32_t*)&ub;
    uint4 o; uint32_t* op = (uint32_t*)&o;
#pragma unroll
    for (int i = 0; i < 4; i++) {
        float2 fa = uph2(ap[i]), fb = uph2(bp[i]);
        op[i] = pkh2(fa.x + fb.x, fa.y + fb.y);
    }
    *(uint4*)(out + (size_t)e * H + c8) = o;
}

// CSR gather segment-sum, fp16 in/out, f32 accumulate, 4-way unrolled
__global__ void segsum_kernel(const __half* __restrict__ rows, const int* __restrict__ rp,
                              const int* __restrict__ ci, __half* __restrict__ out, int nseg) {
    int row = blockIdx.x * 8 + (threadIdx.x >> 5);
    if (row >= nseg) return;
    int lane = threadIdx.x & 31;
    int beg = __ldg(rp + row), end = __ldg(rp + row + 1);
    float a[8] = {0.f,0.f,0.f,0.f,0.f,0.f,0.f,0.f};
    float b[8] = {0.f,0.f,0.f,0.f,0.f,0.f,0.f,0.f};
    int j = beg;
    for (; j + 3 < end; j += 4) {
        uint4 u0 = *(const uint4*)(rows + (size_t)__ldg(ci + j)     * H + lane * 8);
        uint4 u1 = *(const uint4*)(rows + (size_t)__ldg(ci + j + 1) * H + lane * 8);
        uint4 u2 = *(const uint4*)(rows + (size_t)__ldg(ci + j + 2) * H + lane * 8);
        uint4 u3 = *(const uint4*)(rows + (size_t)__ldg(ci + j + 3) * H + lane * 8);
        const uint32_t* p0 = (const uint32_t*)&u0;
        const uint32_t* p1 = (const uint32_t*)&u1;
        const uint32_t* p2 = (const uint32_t*)&u2;
        const uint32_t* p3 = (const uint32_t*)&u3;
#pragma unroll
        for (int i = 0; i < 4; i++) {
            float2 f0 = uph2(p0[i]); a[2*i] += f0.x; a[2*i+1] += f0.y;
            float2 f1 = uph2(p1[i]); b[2*i] += f1.x; b[2*i+1] += f1.y;
            float2 f2 = uph2(p2[i]); a[2*i] += f2.x; a[2*i+1] += f2.y;
            float2 f3 = uph2(p3[i]); b[2*i] += f3.x; b[2*i+1] += f3.y;
        }
    }
    for (; j < end; j++) {
        uint4 u = *(const uint4*)(rows + (size_t)__ldg(ci + j) * H + lane * 8);
        const uint32_t* up = (const uint32_t*)&u;
#pragma unroll
        for (int i = 0; i < 4; i++) {
            float2 f = uph2(up[i]); a[2*i] += f.x; a[2*i+1] += f.y;
        }
    }
    uint4 o; uint32_t* op = (uint32_t*)&o;
#pragma unroll
    for (int i = 0; i < 4; i++) op[i] = pkh2(a[2*i] + b[2*i], a[2*i+1] + b[2*i+1]);
    *(uint4*)(out + (size_t)row * H + lane * 8) = o;
}

__global__ void segsum_rel_kernel(const float* __restrict__ rel, const int* __restrict__ feat,
                                  const int* __restrict__ rp, const int* __restrict__ ci,
                                  __half* __restrict__ out, int nseg) {
    int row = blockIdx.x * 8 + (threadIdx.x >> 5);
    if (row >= nseg) return;
    int lane = threadIdx.x & 31;
    int beg = __ldg(rp + row), end = __ldg(rp + row + 1);
    float a[8] = {0.f,0.f,0.f,0.f,0.f,0.f,0.f,0.f};
    for (int j = beg; j < end; j++) {
        int r = __ldg(feat + __ldg(ci + j));
        const float* p = rel + (size_t)r * H + lane * 8;
        float4 v0 = ((const float4*)p)[0], v1 = ((const float4*)p)[1];
        float2 q;
        q = uph2(pk2(v0.x, v0.y)); a[0] += q.x; a[1] += q.y;
        q = uph2(pk2(v0.z, v0.w)); a[2] += q.x; a[3] += q.y;
        q = uph2(pk2(v1.x, v1.y)); a[4] += q.x; a[5] += q.y;
        q = uph2(pk2(v1.z, v1.w)); a[6] += q.x; a[7] += q.y;
    }
    uint4 o; uint32_t* op = (uint32_t*)&o;
#pragma unroll
    for (int i = 0; i < 4; i++) op[i] = pkh2(a[2*i], a[2*i+1]);
    *(uint4*)(out + (size_t)row * H + lane * 8) = o;
}

// ================= GEMM1 + LN1 fused (fp16), BM=64, 3-stage pipeline, occ 2 ==========
// smem: As 3x2560h (7680h) + Bs 3x8192h (24576h) + 5x256 f32 = 69632 B
#define G1_SMEM_BYTES (64512 + 5 * 1024)

struct G1Args {
    const __half* A[6];
    const __half* W[6];
    const float* Bias[6];
    const __half* xres;
    const float* gamma;
    const float* beta;
};

__global__ void __launch_bounds__(256, 2)
gemm1_ln_kernel(G1Args args, int M, __half* __restrict__ out) {
    extern __shared__ char smraw[];
    __half* As = (__half*)smraw;                // 3 x 2560 halves (stride 40)
    __half* Bs = As + 3 * 2560;                 // 3 x 8192 halves
    float* bias_s = (float*)(Bs + 3 * 8192);
    float* gs  = bias_s + 256;
    float* bt  = gs + 256;
    float* lnS = bt + 256;
    float* lnQ = lnS + 256;
    __half* xs = (__half*)smraw;                // alias after mainloop, stride 264

    int tid = threadIdx.x;
    int bm = blockIdx.x * 64;
    {
        float b = 0.f;
#pragma unroll
        for (int j = 0; j < 6; j++) b += __ldg(args.Bias[j] + tid);
        bias_s[tid] = b;
        gs[tid] = __ldg(args.gamma + tid);
        bt[tid] = __ldg(args.beta + tid);
    }

    uint32_t sbase = (uint32_t)__cvta_generic_to_shared(smraw);
    uint32_t a_base = sbase;
    uint32_t b_base = sbase + 15360;

    int warp = tid >> 5, lane = tid & 31, g = lane >> 2, t = lane & 3;
    int wm = (warp >> 2) * 32;
    int wN = warp & 3;
    int wn = wN * 64;

    float acc[2][8][4];
#pragma unroll
    for (int mt = 0; mt < 2; mt++)
#pragma unroll
        for (int nf = 0; nf < 8; nf++)
#pragma unroll
            for (int i = 0; i < 4; i++) acc[mt][nf][i] = 0.f;

    auto issue = [&](int tt, int buf) {
        int j = tt >> 3, kt = tt & 7;
        const __half* A = args.A[j];
        const uint4* Wp = (const uint4*)args.W[j] + (size_t)kt * 1024;
        {
            int r = tid >> 2, cp = tid & 3;
            int row = bm + r;
            uint32_t dst = a_base + (uint32_t)(buf * 5120 + r * 80 + cp * 16);
            const __half* src = A + (size_t)row * H + kt * 32 + cp * 8;
            int sz = (row < M) ? 16 : 0;
            asm volatile("cp.async.cg.shared.global [%0], [%1], 16, %2;\n"
                         :: "r"(dst), "l"(src), "r"(sz));
        }
#pragma unroll
        for (int i = 0; i < 4; i++) {
            int idx = tid + i * 256;
            uint32_t dst = b_base + (uint32_t)(buf * 16384 + idx * 16);
            asm volatile("cp.async.cg.shared.global [%0], [%1], 16;\n"
                         :: "r"(dst), "l"(Wp + idx));
        }
        asm volatile("cp.async.commit_group;\n");
    };

    issue(0, 0);
    issue(1, 1);
    int buf = 0;
    for (int tt = 0; tt < 48; tt++) {
        if (tt + 1 < 48) {
            asm volatile("cp.async.wait_group 1;\n");
        } else {
            asm volatile("cp.async.wait_group 0;\n");
        }
        __syncthreads();
        if (tt + 2 < 48) {
            int nb = buf + 2; if (nb >= 3) nb -= 3;
            issue(tt + 2, nb);
        }
        const __half* Ab = As + buf * 2560;
        const uint4* Bb4 = (const uint4*)(Bs + buf * 8192) + wN * 128 + lane;
#pragma unroll
        for (int s = 0; s < 2; s++) {
            int k0 = s * 16 + 2 * t;
            const __half* Ar0 = Ab + (wm + g) * 40 + k0;
            const __half* Ar1 = Ab + (wm + 8 + g) * 40 + k0;
            const __half* Ar2 = Ab + (wm + 16 + g) * 40 + k0;
            const __half* Ar3 = Ab + (wm + 24 + g) * 40 + k0;
            uint32_t a0[4], a1[4];
            a0[0] = *(const uint32_t*)Ar0;
            a0[1] = *(const uint32_t*)Ar1;
            a0[2] = *(const uint32_t*)(Ar0 + 8);
            a0[3] = *(const uint32_t*)(Ar1 + 8);
            a1[0] = *(const uint32_t*)Ar2;
            a1[1] = *(const uint32_t*)Ar3;
            a1[2] = *(const uint32_t*)(Ar2 + 8);
            a1[3] = *(const uint32_t*)(Ar3 + 8);
#pragma unroll
            for (int nf4 = 0; nf4 < 4; nf4++) {
                uint4 bv = Bb4[s * 512 + nf4 * 32];
                uint32_t b0[2] = {bv.x, bv.y};
                uint32_t b1[2] = {bv.z, bv.w};
                mma_f16(acc[0][2 * nf4], a0, b0);
                mma_f16(acc[1][2 * nf4], a1, b0);
                mma_f16(acc[0][2 * nf4 + 1], a0, b1);
                mma_f16(acc[1][2 * nf4 + 1], a1, b1);
            }
        }
        if (++buf == 3) buf = 0;
    }
    __syncthreads();

    // residual tile into xs (half, stride 264)
#pragma unroll
    for (int i = 0; i < 8; i++) {
        int idx = tid + i * 256;
        int r = idx >> 5, c8 = (idx & 31) * 8;
        int row = bm + r;
        uint4 v = make_uint4(0, 0, 0, 0);
        if (row < M) v = *(const uint4*)(args.xres + (size_t)row * H + c8);
        *(uint4*)(xs + r * 264 + c8) = v;
    }
    __syncthreads();

#pragma unroll
    for (int mt = 0; mt < 2; mt++) {
#pragma unroll
        for (int h = 0; h < 2; h++) {
            int row = wm + mt * 16 + h * 8 + g;
            float s = 0.f, q = 0.f;
#pragma unroll
            for (int nf = 0; nf < 8; nf++) {
                int col = wn + nf * 8 + 2 * t;
                float2 xv = uph2(*(const uint32_t*)(xs + row * 264 + col));
                float v0 = xv.x + gelu_exact(acc[mt][nf][2 * h]     + bias_s[col]);
                float v1 = xv.y + gelu_exact(acc[mt][nf][2 * h + 1] + bias_s[col + 1]);
                acc[mt][nf][2 * h] = v0; acc[mt][nf][2 * h + 1] = v1;
                s += v0 + v1; q += v0 * v0 + v1 * v1;
            }
#pragma unroll
            for (int o = 1; o <= 2; o <<= 1) {
                s += __shfl_xor_sync(0xffffffffu, s, o);
                q += __shfl_xor_sync(0xffffffffu, q, o);
            }
            if (t == 0) { lnS[row * 4 + wN] = s; lnQ[row * 4 + wN] = q; }
        }
    }
    __syncthreads();
#pragma unroll
    for (int mt = 0; mt < 2; mt++) {
#pragma unroll
        for (int h = 0; h < 2; h++) {
            int row = wm + mt * 16 + h * 8 + g;
            float S = lnS[row * 4] + lnS[row * 4 + 1] + lnS[row * 4 + 2] + lnS[row * 4 + 3];
            float Q = lnQ[row * 4] + lnQ[row * 4 + 1] + lnQ[row * 4 + 2] + lnQ[row * 4 + 3];
            float m = S * (1.f / H), v = Q * (1.f / H) - m * m, rs = rsqrtf(v + 1e-5f);
            if (bm + row < M) {
#pragma unroll
                for (int nf = 0; nf < 8; nf++) {
                    int col = wn + nf * 8 + 2 * t;
                    float o0 = (acc[mt][nf][2 * h]     - m) * rs * gs[col]     + bt[col];
                    float o1 = (acc[mt][nf][2 * h + 1] - m) * rs * gs[col + 1] + bt[col + 1];
                    *(uint32_t*)(out + (size_t)(bm + row) * H + col) = pkh2(o0, o1);
                }
            }
        }
    }
}

// ================= fused FFN + LN2 (fp16), 4 chunks of 256, 3-stage pipelines ========
// smem: xs 16896h + hb 16896h + Bst 3x8192h (24576h) + 2048 f32 = 124928 B
#define F_SMEM_BYTES (116736 + 8192)

struct FArgs {
    const __half* w1;
    const float* b1;
    const __half* w2;
    const float* b2;
    const float* gamma;
    const float* beta;
};

__global__ void __launch_bounds__(512, 1)
ffn_kernel(FArgs args, int M, const __half* __restrict__ in1,
           void* __restrict__ outv, int out_half) {
    extern __shared__ char smraw[];
    __half* xs  = (__half*)smraw;            // 64 x 264 halves
    __half* hb  = xs + 64 * 264;             // 64 x 264 halves (256 used)
    __half* Bst = hb + 64 * 264;             // 3 x 8192 halves
    float* b2s = (float*)(Bst + 3 * 8192);
    float* gs  = b2s + 256;
    float* bt  = gs + 256;
    float* b1c = bt + 256;
    float* lnS = b1c + 256;
    float* lnQ = lnS + 512;

    int tid = threadIdx.x;
    int bm = blockIdx.x * 64;

    if (tid < 256) {
        b2s[tid] = __ldg(args.b2 + tid);
        gs[tid]  = __ldg(args.gamma + tid);
        bt[tid]  = __ldg(args.beta + tid);
    }
#pragma unroll
    for (int i = 0; i < 4; i++) {
        int idx = tid + i * 512;
        int r = idx >> 5, c8 = (idx & 31) * 8;
        int row = bm + r;
        uint4 v = make_uint4(0, 0, 0, 0);
        if (row < M) v = *(const uint4*)(in1 + (size_t)row * H + c8);
        *(uint4*)(xs + r * 264 + c8) = v;
    }

    uint32_t bst_base = (uint32_t)__cvta_generic_to_shared(Bst);
    int warp = tid >> 5, lane = tid & 31, g = lane >> 2, t = lane & 3;
    int wm = (warp >> 3) * 32;
    int wN = warp & 7;
    int wn = wN * 32;

    float acc2[2][4][4];
#pragma unroll
    for (int mt = 0; mt < 2; mt++)
#pragma unroll
        for (int nf = 0; nf < 4; nf++)
#pragma unroll
            for (int i = 0; i < 4; i++) acc2[mt][nf][i] = 0.f;

    __syncthreads();

    for (int c = 0; c < 4; c++) {
        if (c > 0) __syncthreads();   // protect Bst (prior stage2 reads) + b1c before overwrite
        if (tid < 256) b1c[tid] = __ldg(args.b1 + c * 256 + tid);

        float acc1[2][4][4];
#pragma unroll
        for (int mt = 0; mt < 2; mt++)
#pragma unroll
            for (int nf = 0; nf < 4; nf++)
#pragma unroll
                for (int i = 0; i < 4; i++) acc1[mt][nf][i] = 0.f;

        const uint4* W1p = (const uint4*)args.w1 + (size_t)c * 8192;
        auto issue1 = [&](int kt, int buf) {
#pragma unroll
            for (int i = 0; i < 2; i++) {
                int idx = tid + i * 512;
                uint32_t dst = bst_base + (uint32_t)(buf * 16384 + idx * 16);
                asm volatile("cp.async.cg.shared.global [%0], [%1], 16;\n"
                             :: "r"(dst), "l"(W1p + kt * 1024 + idx));
            }
            asm volatile("cp.async.commit_group;\n");
        };

        issue1(0, 0);
        issue1(1, 1);
        int buf1 = 0;
        for (int kt = 0; kt < 8; kt++) {
            if (kt + 1 < 8) {
                asm volatile("cp.async.wait_group 1;\n");
            } else {
                asm volatile("cp.async.wait_group 0;\n");
            }
            __syncthreads();
            if (kt + 2 < 8) {
                int nb = buf1 + 2; if (nb >= 3) nb -= 3;
                issue1(kt + 2, nb);
            }
            const uint4* Bb4 = (const uint4*)(Bst + buf1 * 8192) + wN * 64 + lane;
#pragma unroll
            for (int s = 0; s < 2; s++) {
                int kg = kt * 32 + s * 16 + 2 * t;
                const __half* Ar0 = xs + (wm + g) * 264 + kg;
                const __half* Ar1 = xs + (wm + 8 + g) * 264 + kg;
                const __half* Ar2 = xs + (wm + 16 + g) * 264 + kg;
                const __half* Ar3 = xs + (wm + 24 + g) * 264 + kg;
                uint32_t a0[4], a1[4];
                a0[0] = *(const uint32_t*)Ar0;
                a0[1] = *(const uint32_t*)Ar1;
                a0[2] = *(const uint32_t*)(Ar0 + 8);
                a0[3] = *(const uint32_t*)(Ar1 + 8);
                a1[0] = *(const uint32_t*)Ar2;
                a1[1] = *(const uint32_t*)Ar3;
                a1[2] = *(const uint32_t*)(Ar2 + 8);
                a1[3] = *(const uint32_t*)(Ar3 + 8);
#pragma unroll
                for (int nf4 = 0; nf4 < 2; nf4++) {
                    uint4 bv = Bb4[s * 512 + nf4 * 32];
                    uint32_t b0[2] = {bv.x, bv.y};
                    uint32_t b1[2] = {bv.z, bv.w};
                    mma_f16(acc1[0][2 * nf4], a0, b0);
                    mma_f16(acc1[1][2 * nf4], a1, b0);
                    mma_f16(acc1[0][2 * nf4 + 1], a0, b1);
                    mma_f16(acc1[1][2 * nf4 + 1], a1, b1);
                }
            }
            if (++buf1 == 3) buf1 = 0;
        }

        // h = h16(gelu(acc1 + b1)) -> hb
#pragma unroll
        for (int mt = 0; mt < 2; mt++) {
#pragma unroll
            for (int nf = 0; nf < 4; nf++) {
                int col = wn + nf * 8 + 2 * t;
                float h0 = gelu_exact(acc1[mt][nf][0] + b1c[col]);
                float h1 = gelu_exact(acc1[mt][nf][1] + b1c[col + 1]);
                float h2v = gelu_exact(acc1[mt][nf][2] + b1c[col]);
                float h3v = gelu_exact(acc1[mt][nf][3] + b1c[col + 1]);
                *(uint32_t*)(hb + (wm + mt * 16 + g) * 264 + col)     = pkh2(h0, h1);
                *(uint32_t*)(hb + (wm + mt * 16 + 8 + g) * 264 + col) = pkh2(h2v, h3v);
            }
        }
        __syncthreads();   // hb visible; all stage1 Bst reads done

        const uint4* W2p = (const uint4*)args.w2 + (size_t)c * 8192;
        auto issue2 = [&](int kt, int buf) {
#pragma unroll
            for (int i = 0; i < 2; i++) {
                int idx = tid + i * 512;
                uint32_t dst = bst_base + (uint32_t)(buf * 16384 + idx * 16);
                asm volatile("cp.async.cg.shared.global [%0], [%1], 16;\n"
                             :: "r"(dst), "l"(W2p + kt * 1024 + idx));
            }
            asm volatile("cp.async.commit_group;\n");
        };

        issue2(0, 0);
        issue2(1, 1);
        int buf2 = 0;
        for (int kt = 0; kt < 8; kt++) {
            if (kt + 1 < 8) {
                asm volatile("cp.async.wait_group 1;\n");
            } else {
                asm volatile("cp.async.wait_group 0;\n");
            }
            __syncthreads();
            if (kt + 2 < 8) {
                int nb = buf2 + 2; if (nb >= 3) nb -= 3;
                issue2(kt + 2, nb);
            }
            const uint4* Bb4 = (const uint4*)(Bst + buf2 * 8192) + wN * 64 + lane;
#pragma unroll
            for (int s = 0; s < 2; s++) {
                int kg = kt * 32 + s * 16 + 2 * t;
                const __half* Ar0 = hb + (wm + g) * 264 + kg;
                const __half* Ar1 = hb + (wm + 8 + g) * 264 + kg;
                const __half* Ar2 = hb + (wm + 16 + g) * 264 + kg;
                const __half* Ar3 = hb + (wm + 24 + g) * 264 + kg;
                uint32_t a0[4], a1[4];
                a0[0] = *(const uint32_t*)Ar0;
                a0[1] = *(const uint32_t*)Ar1;
                a0[2] = *(const uint32_t*)(Ar0 + 8);
                a0[3] = *(const uint32_t*)(Ar1 + 8);
                a1[0] = *(const uint32_t*)Ar2;
                a1[1] = *(const uint32_t*)Ar3;
                a1[2] = *(const uint32_t*)(Ar2 + 8);
                a1[3] = *(const uint32_t*)(Ar3 + 8);
#pragma unroll
                for (int nf4 = 0; nf4 < 2; nf4++) {
                    uint4 bv = Bb4[s * 512 + nf4 * 32];
                    uint32_t b0[2] = {bv.x, bv.y};
                    uint32_t b1[2] = {bv.z, bv.w};
                    mma_f16(acc2[0][2 * nf4], a0, b0);
                    mma_f16(acc2[1][2 * nf4], a1, b0);
                    mma_f16(acc2[0][2 * nf4 + 1], a0, b1);
                    mma_f16(acc2[1][2 * nf4 + 1], a1, b1);
                }
            }
            if (++buf2 == 3) buf2 = 0;
        }
    }

    // LN2 epilogue
#pragma unroll
    for (int mt = 0; mt < 2; mt++) {
#pragma unroll
        for (int h = 0; h < 2; h++) {
            int row = wm + mt * 16 + h * 8 + g;
            float s = 0.f, q = 0.f;
#pragma unroll
            for (int nf = 0; nf < 4; nf++) {
                int col = wn + nf * 8 + 2 * t;
                float2 xv = uph2(*(const uint32_t*)(xs + row * 264 + col));
                float v0 = xv.x + acc2[mt][nf][2 * h]     + b2s[col];
                float v1 = xv.y + acc2[mt][nf][2 * h + 1] + b2s[col + 1];
                acc2[mt][nf][2 * h] = v0; acc2[mt][nf][2 * h + 1] = v1;
                s += v0 + v1; q += v0 * v0 + v1 * v1;
            }
#pragma unroll
            for (int o = 1; o <= 2; o <<= 1) {
                s += __shfl_xor_sync(0xffffffffu, s, o);
                q += __shfl_xor_sync(0xffffffffu, q, o);
            }
            if (t == 0) { lnS[row * 8 + wN] = s; lnQ[row * 8 + wN] = q; }
        }
    }
    __syncthreads();
#pragma unroll
    for (int mt = 0; mt < 2; mt++) {
#pragma unroll
        for (int h = 0; h < 2; h++) {
            int row = wm + mt * 16 + h * 8 + g;
            float S = 0.f, Q = 0.f;
#pragma unroll
            for (int i = 0; i < 8; i++) { S += lnS[row * 8 + i]; Q += lnQ[row * 8 + i]; }
            float m = S * (1.f / H), v = Q * (1.f / H) - m * m, rs = rsqrtf(v + 1e-5f);
            if (bm + row < M) {
#pragma unroll
                for (int nf = 0; nf < 4; nf++) {
                    int col = wn + nf * 8 + 2 * t;
                    float o0 = (acc2[mt][nf][2 * h]     - m) * rs * gs[col]     + bt[col];
                    float o1 = (acc2[mt][nf][2 * h + 1] - m) * rs * gs[col + 1] + bt[col + 1];
                    if (out_half) {
                        *(uint32_t*)((__half*)outv + (size_t)(bm + row) * H + col) = pkh2(o0, o1);
                    } else {
                        *(float2*)((float*)outv + (size_t)(bm + row) * H + col) = make_float2(o0, o1);
                    }
                }
            }
        }
    }
}

// ---------------- host orchestration ----------------

struct Net {
    const float *b_self, *b_khop, *b_fuse, *b_ff1, *b_ff2;
    const float *ln1g, *ln1b, *ln2g, *ln2b;
    __half* wbuf;
};

static void run_core(const Net& n, int l, int c, int M, __half* const* z,
                     const __half* xin, const __half* fused, __half* out1buf,
                     void* outp, int out_half, cudaStream_t st) {
    size_t lc = (size_t)(l * 2 + c);
    G1Args ga;
    ga.A[0] = xin;
    ga.W[0] = n.wbuf + OFFH_WSELF + lc * 65536;
    ga.Bias[0] = n.b_self + lc * H;
    for (int i = 0; i < 4; i++) {
        ga.A[1 + i] = z[i];
        ga.W[1 + i] = n.wbuf + OFFH_WKHOP + (lc * 4 + i) * (size_t)65536;
        ga.Bias[1 + i] = n.b_khop + (lc * 4 + i) * (size_t)H;
    }
    ga.A[5] = fused;
    ga.W[5] = n.wbuf + OFFH_WFUSE + lc * 65536;
    ga.Bias[5] = n.b_fuse + lc * H;
    ga.xres = xin;
    ga.gamma = n.ln1g + lc * H;
    ga.beta  = n.ln1b + lc * H;

    gemm1_ln_kernel<<<(M + 63) / 64, 256, G1_SMEM_BYTES, st>>>(ga, M, out1buf);

    FArgs fa;
    fa.w1 = n.wbuf + OFFH_WFF1 + lc * (size_t)262144;
    fa.b1 = n.b_ff1 + lc * FH;
    fa.w2 = n.wbuf + OFFH_WFF2 + lc * (size_t)262144;
    fa.b2 = n.b_ff2 + lc * H;
    fa.gamma = n.ln2g + lc * H;
    fa.beta  = n.ln2b + lc * H;
    ffn_kernel<<<(M + 63) / 64, 512, F_SMEM_BYTES, st>>>(fa, M, out1buf, outp, out_half);
}

static void exclusive_scan(int* cnt, int* rp, int* bsums, int n, cudaStream_t st) {
    int nb = (n + 1023) / 1024;
    scan1_kernel<<<nb, 1024, 0, st>>>(cnt, rp, bsums, n);
    scan2_kernel<<<1, 1024, 0, st>>>(bsums, nb);
    scan3_kernel<<<nb, 1024, 0, st>>>(rp, bsums, cnt, n);
}

extern "C" void kernel_launch(void* const* d_in, const int* in_sizes, int n_in,
                              void* d_out, int out_size) {
    const float* x_in = (const float*)d_in[0];
    const int* feat   = (const int*)d_in[1];
    const int* eig    = (const int*)d_in[2];
    const int* eil    = (const int*)d_in[3];
    const float* rel  = (const float*)d_in[4];

    const float* w_self = (const float*)d_in[5];
    const float* w_khop = (const float*)d_in[7];
    const float* w_fuse = (const float*)d_in[9];
    const float* w_ff1  = (const float*)d_in[11];
    const float* w_ff2  = (const float*)d_in[13];

    Net n;
    n.b_self = (const float*)d_in[6];
    n.b_khop = (const float*)d_in[8];
    n.b_fuse = (const float*)d_in[10];
    n.b_ff1  = (const float*)d_in[12];
    n.b_ff2  = (const float*)d_in[14];
    n.ln1g   = (const float*)d_in[15]; n.ln1b = (const float*)d_in[16];
    n.ln2g   = (const float*)d_in[17]; n.ln2b = (const float*)d_in[18];

    cudaFuncSetAttribute(gemm1_ln_kernel,
                         cudaFuncAttributeMaxDynamicSharedMemorySize, G1_SMEM_BYTES);
    cudaFuncSetAttribute(ffn_kernel,
                         cudaFuncAttributeMaxDynamicSharedMemorySize, F_SMEM_BYTES);

    static cudaStream_t s2 = nullptr;
    static cudaEvent_t ev_start, ev_prep, ev_x0, ev_lg0, ev_fin;
    if (!s2) {
        cudaStreamCreateWithFlags(&s2, cudaStreamNonBlocking);
        cudaEventCreateWithFlags(&ev_start, cudaEventDisableTiming);
        cudaEventCreateWithFlags(&ev_prep,  cudaEventDisableTiming);
        cudaEventCreateWithFlags(&ev_x0,    cudaEventDisableTiming);
        cudaEventCreateWithFlags(&ev_lg0,   cudaEventDisableTiming);
        cudaEventCreateWithFlags(&ev_fin,   cudaEventDisableTiming);
    }

    __half *px0, *plg0, *pfn, *pfe, *pfe2, *pzbase, *pznb, *pout1, *pout1n, *pwbuf;
    int *rp_nd, *ci_nd, *rp_fn, *ci_fn, *rp_lg, *ci_lg;
    int *pcnt, *pcur, *pbs, *pcnt2, *pcur2, *pbs2;
    cudaGetSymbolAddress((void**)&px0,   h_x);
    cudaGetSymbolAddress((void**)&plg0,  h_lg);
    cudaGetSymbolAddress((void**)&pfn,   h_fn);
    cudaGetSymbolAddress((void**)&pfe,   h_fe);
    cudaGetSymbolAddress((void**)&pfe2,  h_fe2);
    cudaGetSymbolAddress((void**)&pzbase,h_z);
    cudaGetSymbolAddress((void**)&pznb,  h_zn);
    cudaGetSymbolAddress((void**)&pout1, h_out1);
    cudaGetSymbolAddress((void**)&pout1n,h_out1n);
    cudaGetSymbolAddress((void**)&pwbuf, g_wbufh);
    cudaGetSymbolAddress((void**)&rp_nd, g_rp_nd);
    cudaGetSymbolAddress((void**)&ci_nd, g_ci_nd);
    cudaGetSymbolAddress((void**)&rp_fn, g_rp_fn);
    cudaGetSymbolAddress((void**)&ci_fn, g_ci_fn);
    cudaGetSymbolAddress((void**)&rp_lg, g_rp_lg);
    cudaGetSymbolAddress((void**)&ci_lg, g_ci_lg);
    cudaGetSymbolAddress((void**)&pcnt,  g_cnt);
    cudaGetSymbolAddress((void**)&pcur,  g_cur);
    cudaGetSymbolAddress((void**)&pbs,   g_bs);
    cudaGetSymbolAddress((void**)&pcnt2, g_cnt2);
    cudaGetSymbolAddress((void**)&pcur2, g_cur2);
    cudaGetSymbolAddress((void**)&pbs2,  g_bs2);

    n.wbuf = pwbuf;
    __half* px[2]  = {px0,  px0  + (size_t)NNODE * H};
    __half* plg[2] = {plg0, plg0 + (size_t)NEDGE * H};
    __half* ze[4]; __half* zn[4];
    for (int i = 0; i < 4; i++) {
        ze[i] = pzbase + (size_t)i * NEDGE * H;
        zn[i] = pznb + (size_t)i * NNODE * H;
    }

    const int* src_g = eig;  const int* dst_g = eig + NEDGE;
    const int* src_l = eil;  const int* dst_l = eil + NLG;

    // fork point for capture
    cudaEventRecord(ev_start, 0);
    cudaStreamWaitEvent(s2, ev_start, 0);

    // ===== stream 0: lg CSR + layer-0 edge khops =====
    cudaMemsetAsync(pcnt, 0, NEDGE * sizeof(int), 0);
    hist_kernel<<<(NLG + 255) / 256, 256>>>(dst_l, pcnt, NLG);
    exclusive_scan(pcnt, rp_lg, pbs, NEDGE, 0);
    cudaMemcpyAsync(pcur, rp_lg, NEDGE * sizeof(int), cudaMemcpyDeviceToDevice, 0);
    fill_kernel<<<(NLG + 255) / 256, 256>>>(dst_l, src_l, pcur, ci_lg, NLG);

    segsum_rel_kernel<<<(NEDGE + 7) / 8, 256>>>(rel, feat, rp_lg, ci_lg, ze[0], NEDGE);
    segsum_kernel<<<(NEDGE + 7) / 8, 256>>>(ze[0], rp_lg, ci_lg, ze[1], NEDGE);
    segsum_kernel<<<(NEDGE + 7) / 8, 256>>>(ze[1], rp_lg, ci_lg, ze[2], NEDGE);
    segsum_kernel<<<(NEDGE + 7) / 8, 256>>>(ze[2], rp_lg, ci_lg, ze[3], NEDGE);

    // ===== stream s2: packs + init + gather2-l0 =====
    cvth_kernel<<<(NNODE * H / 8 + 255) / 256, 256, 0, s2>>>(x_in, px[0], NNODE * H / 8);
    embed_kernel<<<NEDGE * 32 / 256, 256, 0, s2>>>(rel, feat, plg[0]);
    pack256_kernel<<<(4 * 8192 + 255) / 256, 256, 0, s2>>>(w_self, pwbuf + OFFH_WSELF, 4);
    pack256_kernel<<<(16 * 8192 + 255) / 256, 256, 0, s2>>>(w_khop, pwbuf + OFFH_WKHOP, 16);
    pack256_kernel<<<(4 * 8192 + 255) / 256, 256, 0, s2>>>(w_fuse, pwbuf + OFFH_WFUSE, 4);
    packff1_kernel<<<(4 * 32768 + 255) / 256, 256, 0, s2>>>(w_ff1, pwbuf + OFFH_WFF1, 4);
    packff2_kernel<<<(4 * 32768 + 255) / 256, 256, 0, s2>>>(w_ff2, pwbuf + OFFH_WFF2, 4);
    gather2_kernel<<<NEDGE * 32 / 256, 256, 0, s2>>>(px[0], src_g, dst_g, pfe, NEDGE);
    cudaEventRecord(ev_prep, s2);

    // ===== stream s2: node CSRs + node core layer 0 =====
    cudaMemsetAsync(pcnt2, 0, NNODE * sizeof(int), s2);
    hist_kernel<<<(NEDGE + 255) / 256, 256, 0, s2>>>(dst_g, pcnt2, NEDGE);
    exclusive_scan(pcnt2, rp_nd, pbs2, NNODE, s2);
    cudaMemcpyAsync(pcur2, rp_nd, NNODE * sizeof(int), cudaMemcpyDeviceToDevice, s2);
    fill_kernel<<<(NEDGE + 255) / 256, 256, 0, s2>>>(dst_g, src_g, pcur2, ci_nd, NEDGE);

    cudaMemsetAsync(pcnt2, 0, NNODE * sizeof(int), s2);
    hist_kernel<<<(NEDGE + 255) / 256, 256, 0, s2>>>(src_g, pcnt2, NEDGE);
    hist_kernel<<<(NEDGE + 255) / 256, 256, 0, s2>>>(dst_g, pcnt2, NEDGE);
    exclusive_scan(pcnt2, rp_fn, pbs2, NNODE, s2);
    cudaMemcpyAsync(pcur2, rp_fn, NNODE * sizeof(int), cudaMemcpyDeviceToDevice, s2);
    fill_kernel<<<(NEDGE + 255) / 256, 256, 0, s2>>>(src_g, nullptr, pcur2, ci_fn, NEDGE);
    fill_kernel<<<(NEDGE + 255) / 256, 256, 0, s2>>>(dst_g, nullptr, pcur2, ci_fn, NEDGE);

    segsum_kernel<<<(NNODE + 7) / 8, 256, 0, s2>>>(plg[0], rp_fn, ci_fn, pfn, NNODE);
    {
        const __half* prev = px[0];
        for (int i = 0; i < 4; i++) {
            segsum_kernel<<<(NNODE + 7) / 8, 256, 0, s2>>>(prev, rp_nd, ci_nd, zn[i], NNODE);
            prev = zn[i];
        }
    }
    run_core(n, 0, 0, NNODE, zn, px[0], pfn, pout1n, px[1], 1, s2);
    gather2_kernel<<<NEDGE * 32 / 256, 256, 0, s2>>>(px[1], src_g, dst_g, pfe2, NEDGE);
    cudaEventRecord(ev_x0, s2);

    // ===== stream 0: edge core, layer 0 =====
    cudaStreamWaitEvent(0, ev_prep, 0);
    run_core(n, 0, 1, NEDGE, ze, plg[0], pfe, pout1, plg[1], 1, (cudaStream_t)0);
    cudaEventRecord(ev_lg0, 0);

    // ===== stream s2: node core, layer 1 =====
    cudaStreamWaitEvent(s2, ev_lg0, 0);
    segsum_kernel<<<(NNODE + 7) / 8, 256, 0, s2>>>(plg[1], rp_fn, ci_fn, pfn, NNODE);
    {
        const __half* prev = px[1];
        for (int i = 0; i < 4; i++) {
            segsum_kernel<<<(NNODE + 7) / 8, 256, 0, s2>>>(prev, rp_nd, ci_nd, zn[i], NNODE);
            prev = zn[i];
        }
    }
    run_core(n, 1, 0, NNODE, zn, px[1], pfn, pout1n, (float*)d_out, 0, s2);
    cudaEventRecord(ev_fin, s2);

    // ===== stream 0: edge core, layer 1 =====
    {
        const __half* prev = plg[1];
        for (int i = 0; i < 4; i++) {
            segsum_kernel<<<(NEDGE + 7) / 8, 256>>>(prev, rp_lg, ci_lg, ze[i], NEDGE);
            prev = ze[i];
        }
    }
    cudaStreamWaitEvent(0, ev_x0, 0);
    run_core(n, 1, 1, NEDGE, ze, plg[1], pfe2, pout1,
             (float*)d_out + (size_t)NNODE * H, 0, (cudaStream_t)0);

    cudaStreamWaitEvent(0, ev_fin, 0);
    (void)in_sizes; (void)n_in; (void)out_size;
}